// round 5
// baseline (speedup 1.0000x reference)
#include <cuda_runtime.h>
#include <math.h>

#define NN   100000
#define EE   200000
#define KK   4
#define DD   8
#define FEAT 256
#define RANK 64
#define HID  512
#define OUTD 128

// ---------------- scratch (static device arrays; no allocation) ----------------
__device__ float g_scaled[(size_t)NN * RANK];          // num * (X@Wp + bp)        25.6 MB
__device__ float g_emb2[(size_t)NN * OUTD];            // relu(X@W1+b1)@W2 + b2    51.2 MB
__device__ float g_term[(size_t)NN * DD * RANK];       // tanh terms, node-major  204.8 MB
__device__ int   g_eidx[(size_t)NN * DD];              // occurrence -> edge id
__device__ float g_redge2[(size_t)EE * OUTD];          // relu(edge2)             102.4 MB

// ---------------- packed f32x2 helpers ----------------
typedef unsigned long long u64;

__device__ __forceinline__ u64 bcast2(float a) {
    u64 r; asm("mov.b64 %0, {%1, %1};" : "=l"(r) : "f"(a)); return r;
}
__device__ __forceinline__ void upk2(u64 p, float& a, float& b) {
    asm("mov.b64 {%0, %1}, %2;" : "=f"(a), "=f"(b) : "l"(p));
}
__device__ __forceinline__ u64 f2fma(u64 a, u64 b, u64 c) {
    u64 d; asm("fma.rn.f32x2 %0, %1, %2, %3;" : "=l"(d) : "l"(a), "l"(b), "l"(c)); return d;
}

// =====================================================================
// Kernel 1: fused node MLP.
//   g_scaled = num*(X@Wp+bp);  H = relu(X@W1+b1) (smem only);  g_emb2 = H@W2+b2
// Tile: 32 nodes per CTA, 256 threads. smem = X(32KB) + Big(64KB) + Buf(16KB)
// =====================================================================
#define SMEM1 ((32*FEAT + 32*HID + 32*OUTD) * 4)

__global__ __launch_bounds__(256) void node_mlp_kernel(
    const float* __restrict__ X,
    const float* __restrict__ Wp, const float* __restrict__ bp,
    const float* __restrict__ W1, const float* __restrict__ b1,
    const float* __restrict__ W2, const float* __restrict__ b2,
    float num)
{
    extern __shared__ float sm[];
    float* Xs   = sm;                    // [32][256]
    float* Bigs = sm + 32 * FEAT;        // [32][512]  W1 chunks, then H
    float* Buf  = Bigs + 32 * HID;       // [32][128]  Wp / W2 chunks
    const int t  = threadIdx.x;
    const int nb = blockIdx.x * 32;

    // load X tile: 32x256 floats = 2048 float4
    {
        const float4* src = (const float4*)(X + (size_t)nb * FEAT);
        float4* dst = (float4*)Xs;
#pragma unroll
        for (int i = 0; i < 8; i++) dst[t + i * 256] = src[t + i * 256];
    }

    // ---------------- Phase 1: emb1 = num*(X@Wp + bp) -> g_scaled ----------------
    {
        const int row = t >> 3;
        const int c0  = (t & 7) * 8;
        u64 acc[4] = {0, 0, 0, 0};
        for (int kc = 0; kc < FEAT; kc += 32) {
            __syncthreads();
            {   // Wp chunk [32][64] = 512 float4
                const float4* ws = (const float4*)(Wp + kc * RANK);
                float4* wd = (float4*)Buf;
#pragma unroll
                for (int i = 0; i < 2; i++) wd[t + i * 256] = ws[t + i * 256];
            }
            __syncthreads();
#pragma unroll
            for (int k4 = 0; k4 < 8; k4++) {
                float4 a4 = *(const float4*)(Xs + row * FEAT + kc + k4 * 4);
                const float* ap = (const float*)&a4;
#pragma unroll
                for (int kk = 0; kk < 4; kk++) {
                    int k = k4 * 4 + kk;
                    ulonglong2 b01 = *(const ulonglong2*)(Buf + k * RANK + c0);
                    ulonglong2 b23 = *(const ulonglong2*)(Buf + k * RANK + c0 + 4);
                    u64 av = bcast2(ap[kk]);
                    acc[0] = f2fma(av, b01.x, acc[0]);
                    acc[1] = f2fma(av, b01.y, acc[1]);
                    acc[2] = f2fma(av, b23.x, acc[2]);
                    acc[3] = f2fma(av, b23.y, acc[3]);
                }
            }
        }
        float4 bv0 = *(const float4*)(bp + c0);
        float4 bv1 = *(const float4*)(bp + c0 + 4);
        float o[8];
        upk2(acc[0], o[0], o[1]); upk2(acc[1], o[2], o[3]);
        upk2(acc[2], o[4], o[5]); upk2(acc[3], o[6], o[7]);
        float4 w0 = make_float4(num * (o[0] + bv0.x), num * (o[1] + bv0.y),
                                num * (o[2] + bv0.z), num * (o[3] + bv0.w));
        float4 w1v = make_float4(num * (o[4] + bv1.x), num * (o[5] + bv1.y),
                                 num * (o[6] + bv1.z), num * (o[7] + bv1.w));
        *(float4*)(g_scaled + (size_t)(nb + row) * RANK + c0)     = w0;
        *(float4*)(g_scaled + (size_t)(nb + row) * RANK + c0 + 4) = w1v;
    }

    // ---------------- Phase 2: H = relu(X@W1 + b1) -> Bigs ----------------
    {
        const int r0 = (t >> 6) * 8;        // 4 row-groups of 8 rows
        const int c0 = (t & 63) * 8;        // 64 col-groups of 8 cols
        u64 acc[8][4];
#pragma unroll
        for (int i = 0; i < 8; i++)
#pragma unroll
            for (int j = 0; j < 4; j++) acc[i][j] = 0;

        for (int kc = 0; kc < FEAT; kc += 32) {
            __syncthreads();
            {   // W1 chunk [32][512] = 4096 float4
                const float4* ws = (const float4*)(W1 + (size_t)kc * HID);
                float4* wd = (float4*)Bigs;
#pragma unroll
                for (int i = 0; i < 16; i++) wd[t + i * 256] = ws[t + i * 256];
            }
            __syncthreads();
#pragma unroll
            for (int k4 = 0; k4 < 8; k4++) {
                float4 a4[8];
#pragma unroll
                for (int i = 0; i < 8; i++)
                    a4[i] = *(const float4*)(Xs + (r0 + i) * FEAT + kc + k4 * 4);
#pragma unroll
                for (int kk = 0; kk < 4; kk++) {
                    int k = k4 * 4 + kk;
                    ulonglong2 b01 = *(const ulonglong2*)(Bigs + k * HID + c0);
                    ulonglong2 b23 = *(const ulonglong2*)(Bigs + k * HID + c0 + 4);
#pragma unroll
                    for (int i = 0; i < 8; i++) {
                        u64 av = bcast2(((const float*)&a4[i])[kk]);
                        acc[i][0] = f2fma(av, b01.x, acc[i][0]);
                        acc[i][1] = f2fma(av, b01.y, acc[i][1]);
                        acc[i][2] = f2fma(av, b23.x, acc[i][2]);
                        acc[i][3] = f2fma(av, b23.y, acc[i][3]);
                    }
                }
            }
        }
        __syncthreads();   // everyone done reading W1 chunk before H overwrites Bigs
        float4 bv0 = *(const float4*)(b1 + c0);
        float4 bv1 = *(const float4*)(b1 + c0 + 4);
        const float* bb0 = (const float*)&bv0;
        const float* bb1 = (const float*)&bv1;
#pragma unroll
        for (int i = 0; i < 8; i++) {
            float o[8];
            upk2(acc[i][0], o[0], o[1]); upk2(acc[i][1], o[2], o[3]);
            upk2(acc[i][2], o[4], o[5]); upk2(acc[i][3], o[6], o[7]);
            float4 h0, h1;
            h0.x = fmaxf(o[0] + bb0[0], 0.f); h0.y = fmaxf(o[1] + bb0[1], 0.f);
            h0.z = fmaxf(o[2] + bb0[2], 0.f); h0.w = fmaxf(o[3] + bb0[3], 0.f);
            h1.x = fmaxf(o[4] + bb1[0], 0.f); h1.y = fmaxf(o[5] + bb1[1], 0.f);
            h1.z = fmaxf(o[6] + bb1[2], 0.f); h1.w = fmaxf(o[7] + bb1[3], 0.f);
            *(float4*)(Bigs + (r0 + i) * HID + c0)     = h0;
            *(float4*)(Bigs + (r0 + i) * HID + c0 + 4) = h1;
        }
        __syncthreads();
    }

    // ---------------- Phase 3: emb2 = H@W2 + b2 -> g_emb2 ----------------
    {
        const int n0 = (t >> 4) * 2;        // 16 row-pairs
        const int c0 = (t & 15) * 8;        // 16 col-groups
        u64 acc[2][4];
#pragma unroll
        for (int r = 0; r < 2; r++)
#pragma unroll
            for (int j = 0; j < 4; j++) acc[r][j] = 0;

        for (int kc = 0; kc < HID; kc += 32) {
            __syncthreads();
            {   // W2 chunk [32][128] = 1024 float4
                const float4* ws = (const float4*)(W2 + (size_t)kc * OUTD);
                float4* wd = (float4*)Buf;
#pragma unroll
                for (int i = 0; i < 4; i++) wd[t + i * 256] = ws[t + i * 256];
            }
            __syncthreads();
#pragma unroll
            for (int k4 = 0; k4 < 8; k4++) {
                float4 a40 = *(const float4*)(Bigs + n0 * HID + kc + k4 * 4);
                float4 a41 = *(const float4*)(Bigs + (n0 + 1) * HID + kc + k4 * 4);
#pragma unroll
                for (int kk = 0; kk < 4; kk++) {
                    int k = k4 * 4 + kk;
                    ulonglong2 b01 = *(const ulonglong2*)(Buf + k * OUTD + c0);
                    ulonglong2 b23 = *(const ulonglong2*)(Buf + k * OUTD + c0 + 4);
                    u64 av0 = bcast2(((const float*)&a40)[kk]);
                    u64 av1 = bcast2(((const float*)&a41)[kk]);
                    acc[0][0] = f2fma(av0, b01.x, acc[0][0]);
                    acc[0][1] = f2fma(av0, b01.y, acc[0][1]);
                    acc[0][2] = f2fma(av0, b23.x, acc[0][2]);
                    acc[0][3] = f2fma(av0, b23.y, acc[0][3]);
                    acc[1][0] = f2fma(av1, b01.x, acc[1][0]);
                    acc[1][1] = f2fma(av1, b01.y, acc[1][1]);
                    acc[1][2] = f2fma(av1, b23.x, acc[1][2]);
                    acc[1][3] = f2fma(av1, b23.y, acc[1][3]);
                }
            }
        }
        float4 bv0 = *(const float4*)(b2 + c0);
        float4 bv1 = *(const float4*)(b2 + c0 + 4);
        const float* bb0 = (const float*)&bv0;
        const float* bb1 = (const float*)&bv1;
#pragma unroll
        for (int r = 0; r < 2; r++) {
            float o[8];
            upk2(acc[r][0], o[0], o[1]); upk2(acc[r][1], o[2], o[3]);
            upk2(acc[r][2], o[4], o[5]); upk2(acc[r][3], o[6], o[7]);
            float4 w0 = make_float4(o[0] + bb0[0], o[1] + bb0[1], o[2] + bb0[2], o[3] + bb0[3]);
            float4 w1v = make_float4(o[4] + bb1[0], o[5] + bb1[1], o[6] + bb1[2], o[7] + bb1[3]);
            *(float4*)(g_emb2 + (size_t)(nb + n0 + r) * OUTD + c0)     = w0;
            *(float4*)(g_emb2 + (size_t)(nb + n0 + r) * OUTD + c0 + 4) = w1v;
        }
    }
}

// =====================================================================
// Kernel 2: per-edge. One warp per edge. Computes leave-one-out products,
// tanh terms (scattered deterministically to node-major g_term via the
// permutation-block slot d = e / (N/K)), and relu(edge2) -> g_redge2.
// =====================================================================
__global__ __launch_bounds__(256) void edge_kernel(
    const int* __restrict__ en, float C, int perm_edges)
{
    const int lane = threadIdx.x & 31;
    const int e    = blockIdx.x * 8 + (threadIdx.x >> 5);

    int myn = 0;
    if (lane < 4) myn = en[e * 4 + lane];
    const unsigned m = 0xffffffffu;
    int n0 = __shfl_sync(m, myn, 0);
    int n1 = __shfl_sync(m, myn, 1);
    int n2 = __shfl_sync(m, myn, 2);
    int n3 = __shfl_sync(m, myn, 3);

    float2 g0 = *(const float2*)(g_scaled + (size_t)n0 * RANK + lane * 2);
    float2 g1 = *(const float2*)(g_scaled + (size_t)n1 * RANK + lane * 2);
    float2 g2 = *(const float2*)(g_scaled + (size_t)n2 * RANK + lane * 2);
    float2 g3 = *(const float2*)(g_scaled + (size_t)n3 * RANK + lane * 2);

    float2 a, b;
    a.x = g0.x * g1.x; a.y = g0.y * g1.y;     // g0*g1
    b.x = g2.x * g3.x; b.y = g2.y * g3.y;     // g2*g3
    float2 t0, t1, t2, t3;
    t0.x = tanhf(C * (g1.x * b.x)); t0.y = tanhf(C * (g1.y * b.y));
    t1.x = tanhf(C * (g0.x * b.x)); t1.y = tanhf(C * (g0.y * b.y));
    t2.x = tanhf(C * (a.x * g3.x)); t2.y = tanhf(C * (a.y * g3.y));
    t3.x = tanhf(C * (a.x * g2.x)); t3.y = tanhf(C * (a.y * g2.y));

    const int d = e / perm_edges;   // slot: each node appears once per permutation block
    *(float2*)(g_term + ((size_t)n0 * DD + d) * RANK + lane * 2) = t0;
    *(float2*)(g_term + ((size_t)n1 * DD + d) * RANK + lane * 2) = t1;
    *(float2*)(g_term + ((size_t)n2 * DD + d) * RANK + lane * 2) = t2;
    *(float2*)(g_term + ((size_t)n3 * DD + d) * RANK + lane * 2) = t3;
    if (lane < 4) g_eidx[(size_t)myn * DD + d] = e;

    // edge2 = sum emb2[members]; relu; store per edge
    float4 s = make_float4(0.f, 0.f, 0.f, 0.f);
    float4 v;
    v = *(const float4*)(g_emb2 + (size_t)n0 * OUTD + lane * 4);
    s.x += v.x; s.y += v.y; s.z += v.z; s.w += v.w;
    v = *(const float4*)(g_emb2 + (size_t)n1 * OUTD + lane * 4);
    s.x += v.x; s.y += v.y; s.z += v.z; s.w += v.w;
    v = *(const float4*)(g_emb2 + (size_t)n2 * OUTD + lane * 4);
    s.x += v.x; s.y += v.y; s.z += v.z; s.w += v.w;
    v = *(const float4*)(g_emb2 + (size_t)n3 * OUTD + lane * 4);
    s.x += v.x; s.y += v.y; s.z += v.z; s.w += v.w;
    s.x = fmaxf(s.x, 0.f); s.y = fmaxf(s.y, 0.f);
    s.z = fmaxf(s.z, 0.f); s.w = fmaxf(s.w, 0.f);
    *(float4*)(g_redge2 + (size_t)e * OUTD + lane * 4) = s;
}

// =====================================================================
// Kernel 3: per-node output. tsum = sum_d term; out = relu((tsum@Wq +
// D*bq + sum_d redge2)/D). 32 nodes per CTA.
// =====================================================================
__global__ __launch_bounds__(256) void out_kernel(
    const float* __restrict__ Wq, const float* __restrict__ bq,
    float* __restrict__ out, float degf, float invdeg)
{
    __shared__ float tsums[32 * RANK];      // 8 KB
    __shared__ float Wqs[RANK * OUTD];      // 32 KB
    __shared__ int   eixs[32 * DD];         // 1 KB
    const int t  = threadIdx.x;
    const int nb = blockIdx.x * 32;

    {   // Wq: 8192 floats = 2048 float4
        const float4* ws = (const float4*)Wq;
        float4* wd = (float4*)Wqs;
#pragma unroll
        for (int i = 0; i < 8; i++) wd[t + i * 256] = ws[t + i * 256];
    }
    eixs[t] = g_eidx[(size_t)nb * DD + t];

    {   // tsum: node n (t>>3), cols (t&7)*8 .. +7, summed over 8 slots
        const int n = t >> 3;
        const int p = (t & 7) * 8;
        const float* src = g_term + (size_t)(nb + n) * DD * RANK + p;
        float4 s0 = make_float4(0.f, 0.f, 0.f, 0.f);
        float4 s1 = make_float4(0.f, 0.f, 0.f, 0.f);
#pragma unroll
        for (int d = 0; d < DD; d++) {
            float4 v0 = *(const float4*)(src + d * RANK);
            float4 v1 = *(const float4*)(src + d * RANK + 4);
            s0.x += v0.x; s0.y += v0.y; s0.z += v0.z; s0.w += v0.w;
            s1.x += v1.x; s1.y += v1.y; s1.z += v1.z; s1.w += v1.w;
        }
        *(float4*)(tsums + n * RANK + p)     = s0;
        *(float4*)(tsums + n * RANK + p + 4) = s1;
    }
    __syncthreads();

    const int n0 = (t >> 4) * 2;
    const int c0 = (t & 15) * 8;
    u64 acc[2][4];
#pragma unroll
    for (int r = 0; r < 2; r++)
#pragma unroll
        for (int j = 0; j < 4; j++) acc[r][j] = 0;

#pragma unroll
    for (int k4 = 0; k4 < RANK / 4; k4++) {
        float4 a40 = *(const float4*)(tsums + n0 * RANK + k4 * 4);
        float4 a41 = *(const float4*)(tsums + (n0 + 1) * RANK + k4 * 4);
#pragma unroll
        for (int kk = 0; kk < 4; kk++) {
            int k = k4 * 4 + kk;
            ulonglong2 b01 = *(const ulonglong2*)(Wqs + k * OUTD + c0);
            ulonglong2 b23 = *(const ulonglong2*)(Wqs + k * OUTD + c0 + 4);
            u64 av0 = bcast2(((const float*)&a40)[kk]);
            u64 av1 = bcast2(((const float*)&a41)[kk]);
            acc[0][0] = f2fma(av0, b01.x, acc[0][0]);
            acc[0][1] = f2fma(av0, b01.y, acc[0][1]);
            acc[0][2] = f2fma(av0, b23.x, acc[0][2]);
            acc[0][3] = f2fma(av0, b23.y, acc[0][3]);
            acc[1][0] = f2fma(av1, b01.x, acc[1][0]);
            acc[1][1] = f2fma(av1, b01.y, acc[1][1]);
            acc[1][2] = f2fma(av1, b23.x, acc[1][2]);
            acc[1][3] = f2fma(av1, b23.y, acc[1][3]);
        }
    }

    float4 bv0 = *(const float4*)(bq + c0);
    float4 bv1 = *(const float4*)(bq + c0 + 4);
    const float* bb0 = (const float*)&bv0;
    const float* bb1 = (const float*)&bv1;

#pragma unroll
    for (int r = 0; r < 2; r++) {
        const int n = n0 + r;
        float4 r0 = make_float4(0.f, 0.f, 0.f, 0.f);
        float4 r1 = make_float4(0.f, 0.f, 0.f, 0.f);
#pragma unroll
        for (int d = 0; d < DD; d++) {
            int e = eixs[n * DD + d];
            float4 v0 = *(const float4*)(g_redge2 + (size_t)e * OUTD + c0);
            float4 v1 = *(const float4*)(g_redge2 + (size_t)e * OUTD + c0 + 4);
            r0.x += v0.x; r0.y += v0.y; r0.z += v0.z; r0.w += v0.w;
            r1.x += v1.x; r1.y += v1.y; r1.z += v1.z; r1.w += v1.w;
        }
        float o[8];
        upk2(acc[r][0], o[0], o[1]); upk2(acc[r][1], o[2], o[3]);
        upk2(acc[r][2], o[4], o[5]); upk2(acc[r][3], o[6], o[7]);
        const float* rr0 = (const float*)&r0;
        const float* rr1 = (const float*)&r1;
        float4 w0, w1v;
        w0.x = fmaxf((o[0] + degf * bb0[0] + rr0[0]) * invdeg, 0.f);
        w0.y = fmaxf((o[1] + degf * bb0[1] + rr0[1]) * invdeg, 0.f);
        w0.z = fmaxf((o[2] + degf * bb0[2] + rr0[2]) * invdeg, 0.f);
        w0.w = fmaxf((o[3] + degf * bb0[3] + rr0[3]) * invdeg, 0.f);
        w1v.x = fmaxf((o[4] + degf * bb1[0] + rr1[0]) * invdeg, 0.f);
        w1v.y = fmaxf((o[5] + degf * bb1[1] + rr1[1]) * invdeg, 0.f);
        w1v.z = fmaxf((o[6] + degf * bb1[2] + rr1[2]) * invdeg, 0.f);
        w1v.w = fmaxf((o[7] + degf * bb1[3] + rr1[3]) * invdeg, 0.f);
        *(float4*)(out + (size_t)(nb + n) * OUTD + c0)     = w0;
        *(float4*)(out + (size_t)(nb + n) * OUTD + c0 + 4) = w1v;
    }
}

// =====================================================================
extern "C" void kernel_launch(void* const* d_in, const int* in_sizes, int n_in,
                              void* d_out, int out_size)
{
    const float* X  = (const float*)d_in[0];
    const float* Wp = (const float*)d_in[1];
    const float* bp = (const float*)d_in[2];
    const float* Wq = (const float*)d_in[3];
    const float* bq = (const float*)d_in[4];
    const float* W1 = (const float*)d_in[5];
    const float* b1 = (const float*)d_in[6];
    const float* W2 = (const float*)d_in[7];
    const float* b2 = (const float*)d_in[8];
    const int*   en = (const int*)d_in[9];

    const int N  = in_sizes[0] / FEAT;      // 100000
    const int EK = in_sizes[9];             // 800000
    const int E  = EK / KK;                 // 200000
    const int deg = EK / N;                 // 8
    const float num = powf((float)deg, 1.0f / (float)KK);  // deg^(1/K)
    const float C   = num * (1.0f / 6.0f);                 // inv_fact(K-1)! * num
    const int perm_edges = N / KK;          // 25000 edges per permutation block

    cudaFuncSetAttribute(node_mlp_kernel,
                         cudaFuncAttributeMaxDynamicSharedMemorySize, SMEM1);

    node_mlp_kernel<<<N / 32, 256, SMEM1>>>(X, Wp, bp, W1, b1, W2, b2, num);
    edge_kernel<<<E / 8, 256>>>(en, C, perm_edges);
    out_kernel<<<N / 32, 256>>>(Wq, bq, (float*)d_out, (float)deg, 1.0f / (float)deg);
}

// round 7
// speedup vs baseline: 1.4417x; 1.4417x over previous
#include <cuda_runtime.h>
#include <math.h>

#define NN   100000
#define EE   200000
#define KK   4
#define DD   8
#define FEAT 256
#define RANK 64
#define HID  512
#define OUTD 128

// ---------------- scratch (static device arrays; no allocation) ----------------
__device__ float g_scaled[(size_t)NN * RANK];
__device__ float g_emb2[(size_t)NN * OUTD];
__device__ float g_term[(size_t)NN * DD * RANK];
__device__ int   g_eidx[(size_t)NN * DD];
__device__ float g_redge2[(size_t)EE * OUTD];

// ---------------- packed f32x2 helpers ----------------
typedef unsigned long long u64;

__device__ __forceinline__ u64 bcast2(float a) {
    u64 r; asm("mov.b64 %0, {%1, %1};" : "=l"(r) : "f"(a)); return r;
}
__device__ __forceinline__ void upk2(u64 p, float& a, float& b) {
    asm("mov.b64 {%0, %1}, %2;" : "=f"(a), "=f"(b) : "l"(p));
}
__device__ __forceinline__ u64 f2fma(u64 a, u64 b, u64 c) {
    u64 d; asm("fma.rn.f32x2 %0, %1, %2, %3;" : "=l"(d) : "l"(a), "l"(b), "l"(c)); return d;
}

// =====================================================================
// Kernel 1: fused node MLP, conflict-free smem layout + double-buffered
// weight staging. 32 nodes/CTA, 256 threads.
// smem = Xs 32KB + Bigs 64KB (W1 ping/pong -> H) + Buf 16KB (Wp/W2 ping/pong)
// =====================================================================
#define SMEM1 ((32*FEAT + 32*HID + 32*OUTD) * 4)

__global__ __launch_bounds__(256) void node_mlp_kernel(
    const float* __restrict__ X,
    const float* __restrict__ Wp, const float* __restrict__ bp,
    const float* __restrict__ W1, const float* __restrict__ b1,
    const float* __restrict__ W2, const float* __restrict__ b2,
    float num)
{
    extern __shared__ float sm[];
    float* Xs   = sm;                    // [32][256]
    float* Bigs = sm + 32 * FEAT;        // [32][512]
    float* Buf  = Bigs + 32 * HID;       // [32][128]
    const int t  = threadIdx.x;
    const int nb = blockIdx.x * 32;

    {
        const float4* src = (const float4*)(X + (size_t)nb * FEAT);
        float4* dst = (float4*)Xs;
#pragma unroll
        for (int i = 0; i < 8; i++) dst[t + i * 256] = src[t + i * 256];
    }

    // ---------------- Phase 1: emb1 = num*(X@Wp + bp) -> g_scaled ----------------
    {
        const int row = t >> 3;
        const int g   = t & 7;
        float* P0 = Buf;
        float* P1 = Buf + 32 * RANK;
        float4 stg[2];
        {
            const float4* src = (const float4*)Wp;
            stg[0] = src[t]; stg[1] = src[t + 256];
            float4* dst = (float4*)P0;
            dst[t] = stg[0]; dst[t + 256] = stg[1];
        }
        __syncthreads();

        u64 acc[4] = {0, 0, 0, 0};
        for (int c = 0; c < 8; c++) {
            if (c < 7) {
                const float4* src = (const float4*)(Wp + (size_t)(c + 1) * 32 * RANK);
                stg[0] = src[t]; stg[1] = src[t + 256];
            }
            const float* bc = (c & 1) ? P1 : P0;
#pragma unroll
            for (int k4 = 0; k4 < 8; k4++) {
                float4 a4 = *(const float4*)(Xs + row * FEAT + c * 32 + k4 * 4);
                const float* ap = (const float*)&a4;
#pragma unroll
                for (int kk = 0; kk < 4; kk++) {
                    int k = k4 * 4 + kk;
                    ulonglong2 b0 = *(const ulonglong2*)(bc + k * RANK + 4 * g);
                    ulonglong2 b1v = *(const ulonglong2*)(bc + k * RANK + 32 + 4 * g);
                    u64 av = bcast2(ap[kk]);
                    acc[0] = f2fma(av, b0.x,  acc[0]);
                    acc[1] = f2fma(av, b0.y,  acc[1]);
                    acc[2] = f2fma(av, b1v.x, acc[2]);
                    acc[3] = f2fma(av, b1v.y, acc[3]);
                }
            }
            if (c < 7) {
                float4* dst = (float4*)((c & 1) ? P0 : P1);
                dst[t] = stg[0]; dst[t + 256] = stg[1];
            }
            __syncthreads();
        }
        float4 bv0 = *(const float4*)(bp + 4 * g);
        float4 bv1 = *(const float4*)(bp + 32 + 4 * g);
        float o[8];
        upk2(acc[0], o[0], o[1]); upk2(acc[1], o[2], o[3]);
        upk2(acc[2], o[4], o[5]); upk2(acc[3], o[6], o[7]);
        float4 w0 = make_float4(num * (o[0] + bv0.x), num * (o[1] + bv0.y),
                                num * (o[2] + bv0.z), num * (o[3] + bv0.w));
        float4 w1v = make_float4(num * (o[4] + bv1.x), num * (o[5] + bv1.y),
                                 num * (o[6] + bv1.z), num * (o[7] + bv1.w));
        *(float4*)(g_scaled + (size_t)(nb + row) * RANK + 4 * g)      = w0;
        *(float4*)(g_scaled + (size_t)(nb + row) * RANK + 32 + 4 * g) = w1v;
    }

    // ---------------- Phase 2: H = relu(X@W1 + b1) -> Bigs ----------------
    {
        const int g2 = t & 63;
        const int r0 = (t >> 6) * 8;
        float* BA = Bigs;
        float* BB = Bigs + 16 * HID;
        float4 stg[8];
        {
            const float4* src = (const float4*)W1;
#pragma unroll
            for (int i = 0; i < 8; i++) stg[i] = src[t + i * 256];
            float4* dst = (float4*)BA;
#pragma unroll
            for (int i = 0; i < 8; i++) dst[t + i * 256] = stg[i];
        }
        __syncthreads();

        u64 acc[8][4];
#pragma unroll
        for (int i = 0; i < 8; i++)
#pragma unroll
            for (int j = 0; j < 4; j++) acc[i][j] = 0;

        for (int c = 0; c < 16; c++) {
            if (c < 15) {
                const float4* src = (const float4*)(W1 + (size_t)(c + 1) * 16 * HID);
#pragma unroll
                for (int i = 0; i < 8; i++) stg[i] = src[t + i * 256];
            }
            const float* bc = (c & 1) ? BB : BA;
#pragma unroll
            for (int k4 = 0; k4 < 4; k4++) {
                float4 a4[8];
#pragma unroll
                for (int i = 0; i < 8; i++)
                    a4[i] = *(const float4*)(Xs + (r0 + i) * FEAT + c * 16 + k4 * 4);
#pragma unroll
                for (int kk = 0; kk < 4; kk++) {
                    int k = k4 * 4 + kk;
                    ulonglong2 b0 = *(const ulonglong2*)(bc + k * HID + 4 * g2);
                    ulonglong2 b1v = *(const ulonglong2*)(bc + k * HID + 256 + 4 * g2);
#pragma unroll
                    for (int i = 0; i < 8; i++) {
                        u64 av = bcast2(((const float*)&a4[i])[kk]);
                        acc[i][0] = f2fma(av, b0.x,  acc[i][0]);
                        acc[i][1] = f2fma(av, b0.y,  acc[i][1]);
                        acc[i][2] = f2fma(av, b1v.x, acc[i][2]);
                        acc[i][3] = f2fma(av, b1v.y, acc[i][3]);
                    }
                }
            }
            if (c < 15) {
                float4* dst = (float4*)((c & 1) ? BA : BB);
#pragma unroll
                for (int i = 0; i < 8; i++) dst[t + i * 256] = stg[i];
            }
            __syncthreads();
        }

        float4 bv0 = *(const float4*)(b1 + 4 * g2);
        float4 bv1 = *(const float4*)(b1 + 256 + 4 * g2);
        const float* bb0 = (const float*)&bv0;
        const float* bb1 = (const float*)&bv1;
#pragma unroll
        for (int i = 0; i < 8; i++) {
            float o[8];
            upk2(acc[i][0], o[0], o[1]); upk2(acc[i][1], o[2], o[3]);
            upk2(acc[i][2], o[4], o[5]); upk2(acc[i][3], o[6], o[7]);
            float4 h0, h1;
            h0.x = fmaxf(o[0] + bb0[0], 0.f); h0.y = fmaxf(o[1] + bb0[1], 0.f);
            h0.z = fmaxf(o[2] + bb0[2], 0.f); h0.w = fmaxf(o[3] + bb0[3], 0.f);
            h1.x = fmaxf(o[4] + bb1[0], 0.f); h1.y = fmaxf(o[5] + bb1[1], 0.f);
            h1.z = fmaxf(o[6] + bb1[2], 0.f); h1.w = fmaxf(o[7] + bb1[3], 0.f);
            *(float4*)(Bigs + (r0 + i) * HID + 4 * g2)       = h0;
            *(float4*)(Bigs + (r0 + i) * HID + 256 + 4 * g2) = h1;
        }
        __syncthreads();
    }

    // ---------------- Phase 3: emb2 = H@W2 + b2 -> g_emb2 ----------------
    {
        const int n0 = (t >> 4) * 2;
        const int cg = t & 15;
        float* CA = Buf;
        float* CB = Buf + 16 * OUTD;
        float4 stg[2];
        {
            const float4* src = (const float4*)W2;
            stg[0] = src[t]; stg[1] = src[t + 256];
            float4* dst = (float4*)CA;
            dst[t] = stg[0]; dst[t + 256] = stg[1];
        }
        __syncthreads();

        u64 acc[2][4];
#pragma unroll
        for (int r = 0; r < 2; r++)
#pragma unroll
            for (int j = 0; j < 4; j++) acc[r][j] = 0;

        for (int c = 0; c < 32; c++) {
            if (c < 31) {
                const float4* src = (const float4*)(W2 + (size_t)(c + 1) * 16 * OUTD);
                stg[0] = src[t]; stg[1] = src[t + 256];
            }
            const float* bc = (c & 1) ? CB : CA;
#pragma unroll
            for (int k4 = 0; k4 < 4; k4++) {
                float4 a40 = *(const float4*)(Bigs + n0 * HID + c * 16 + k4 * 4);
                float4 a41 = *(const float4*)(Bigs + (n0 + 1) * HID + c * 16 + k4 * 4);
#pragma unroll
                for (int kk = 0; kk < 4; kk++) {
                    int k = k4 * 4 + kk;
                    ulonglong2 b0 = *(const ulonglong2*)(bc + k * OUTD + 4 * cg);
                    ulonglong2 b1v = *(const ulonglong2*)(bc + k * OUTD + 64 + 4 * cg);
                    u64 av0 = bcast2(((const float*)&a40)[kk]);
                    u64 av1 = bcast2(((const float*)&a41)[kk]);
                    acc[0][0] = f2fma(av0, b0.x,  acc[0][0]);
                    acc[0][1] = f2fma(av0, b0.y,  acc[0][1]);
                    acc[0][2] = f2fma(av0, b1v.x, acc[0][2]);
                    acc[0][3] = f2fma(av0, b1v.y, acc[0][3]);
                    acc[1][0] = f2fma(av1, b0.x,  acc[1][0]);
                    acc[1][1] = f2fma(av1, b0.y,  acc[1][1]);
                    acc[1][2] = f2fma(av1, b1v.x, acc[1][2]);
                    acc[1][3] = f2fma(av1, b1v.y, acc[1][3]);
                }
            }
            if (c < 31) {
                float4* dst = (float4*)((c & 1) ? CA : CB);
                dst[t] = stg[0]; dst[t + 256] = stg[1];
            }
            __syncthreads();
        }

        float4 bv0 = *(const float4*)(b2 + 4 * cg);
        float4 bv1 = *(const float4*)(b2 + 64 + 4 * cg);
        const float* bb0 = (const float*)&bv0;
        const float* bb1 = (const float*)&bv1;
#pragma unroll
        for (int r = 0; r < 2; r++) {
            float o[8];
            upk2(acc[r][0], o[0], o[1]); upk2(acc[r][1], o[2], o[3]);
            upk2(acc[r][2], o[4], o[5]); upk2(acc[r][3], o[6], o[7]);
            float4 w0 = make_float4(o[0] + bb0[0], o[1] + bb0[1],
                                    o[2] + bb0[2], o[3] + bb0[3]);
            float4 w1v = make_float4(o[4] + bb1[0], o[5] + bb1[1],
                                     o[6] + bb1[2], o[7] + bb1[3]);
            *(float4*)(g_emb2 + (size_t)(nb + n0 + r) * OUTD + 4 * cg)      = w0;
            *(float4*)(g_emb2 + (size_t)(nb + n0 + r) * OUTD + 64 + 4 * cg) = w1v;
        }
    }
}

// =====================================================================
// Kernel 2: per-edge (unchanged).
// =====================================================================
__global__ __launch_bounds__(256) void edge_kernel(
    const int* __restrict__ en, float C, int perm_edges)
{
    const int lane = threadIdx.x & 31;
    const int e    = blockIdx.x * 8 + (threadIdx.x >> 5);

    int myn = 0;
    if (lane < 4) myn = en[e * 4 + lane];
    const unsigned m = 0xffffffffu;
    int n0 = __shfl_sync(m, myn, 0);
    int n1 = __shfl_sync(m, myn, 1);
    int n2 = __shfl_sync(m, myn, 2);
    int n3 = __shfl_sync(m, myn, 3);

    float2 g0 = *(const float2*)(g_scaled + (size_t)n0 * RANK + lane * 2);
    float2 g1 = *(const float2*)(g_scaled + (size_t)n1 * RANK + lane * 2);
    float2 g2 = *(const float2*)(g_scaled + (size_t)n2 * RANK + lane * 2);
    float2 g3 = *(const float2*)(g_scaled + (size_t)n3 * RANK + lane * 2);

    float2 a, b;
    a.x = g0.x * g1.x; a.y = g0.y * g1.y;
    b.x = g2.x * g3.x; b.y = g2.y * g3.y;
    float2 t0, t1, t2, t3;
    t0.x = tanhf(C * (g1.x * b.x)); t0.y = tanhf(C * (g1.y * b.y));
    t1.x = tanhf(C * (g0.x * b.x)); t1.y = tanhf(C * (g0.y * b.y));
    t2.x = tanhf(C * (a.x * g3.x)); t2.y = tanhf(C * (a.y * g3.y));
    t3.x = tanhf(C * (a.x * g2.x)); t3.y = tanhf(C * (a.y * g2.y));

    const int d = e / perm_edges;
    *(float2*)(g_term + ((size_t)n0 * DD + d) * RANK + lane * 2) = t0;
    *(float2*)(g_term + ((size_t)n1 * DD + d) * RANK + lane * 2) = t1;
    *(float2*)(g_term + ((size_t)n2 * DD + d) * RANK + lane * 2) = t2;
    *(float2*)(g_term + ((size_t)n3 * DD + d) * RANK + lane * 2) = t3;
    if (lane < 4) g_eidx[(size_t)myn * DD + d] = e;

    float4 s = make_float4(0.f, 0.f, 0.f, 0.f);
    float4 v;
    v = *(const float4*)(g_emb2 + (size_t)n0 * OUTD + lane * 4);
    s.x += v.x; s.y += v.y; s.z += v.z; s.w += v.w;
    v = *(const float4*)(g_emb2 + (size_t)n1 * OUTD + lane * 4);
    s.x += v.x; s.y += v.y; s.z += v.z; s.w += v.w;
    v = *(const float4*)(g_emb2 + (size_t)n2 * OUTD + lane * 4);
    s.x += v.x; s.y += v.y; s.z += v.z; s.w += v.w;
    v = *(const float4*)(g_emb2 + (size_t)n3 * OUTD + lane * 4);
    s.x += v.x; s.y += v.y; s.z += v.z; s.w += v.w;
    s.x = fmaxf(s.x, 0.f); s.y = fmaxf(s.y, 0.f);
    s.z = fmaxf(s.z, 0.f); s.w = fmaxf(s.w, 0.f);
    *(float4*)(g_redge2 + (size_t)e * OUTD + lane * 4) = s;
}

// =====================================================================
// Kernel 3: per-node output, conflict-free Wq column ownership.
// =====================================================================
__global__ __launch_bounds__(256) void out_kernel(
    const float* __restrict__ Wq, const float* __restrict__ bq,
    float* __restrict__ out, float degf, float invdeg)
{
    __shared__ float tsums[32 * RANK];
    __shared__ float Wqs[RANK * OUTD];
    __shared__ int   eixs[32 * DD];
    const int t  = threadIdx.x;
    const int nb = blockIdx.x * 32;

    {
        const float4* ws = (const float4*)Wq;
        float4* wd = (float4*)Wqs;
#pragma unroll
        for (int i = 0; i < 8; i++) wd[t + i * 256] = ws[t + i * 256];
    }
    eixs[t] = g_eidx[(size_t)nb * DD + t];

    {
        const int n = t >> 3;
        const int p = (t & 7) * 8;
        const float* src = g_term + (size_t)(nb + n) * DD * RANK + p;
        float4 s0 = make_float4(0.f, 0.f, 0.f, 0.f);
        float4 s1 = make_float4(0.f, 0.f, 0.f, 0.f);
#pragma unroll
        for (int d = 0; d < DD; d++) {
            float4 v0 = *(const float4*)(src + d * RANK);
            float4 v1 = *(const float4*)(src + d * RANK + 4);
            s0.x += v0.x; s0.y += v0.y; s0.z += v0.z; s0.w += v0.w;
            s1.x += v1.x; s1.y += v1.y; s1.z += v1.z; s1.w += v1.w;
        }
        *(float4*)(tsums + n * RANK + p)     = s0;
        *(float4*)(tsums + n * RANK + p + 4) = s1;
    }
    __syncthreads();

    const int n0 = (t >> 4) * 2;
    const int cg = t & 15;
    u64 acc[2][4];
#pragma unroll
    for (int r = 0; r < 2; r++)
#pragma unroll
        for (int j = 0; j < 4; j++) acc[r][j] = 0;

#pragma unroll
    for (int k4 = 0; k4 < RANK / 4; k4++) {
        float4 a40 = *(const float4*)(tsums + n0 * RANK + k4 * 4);
        float4 a41 = *(const float4*)(tsums + (n0 + 1) * RANK + k4 * 4);
#pragma unroll
        for (int kk = 0; kk < 4; kk++) {
            int k = k4 * 4 + kk;
            ulonglong2 b0 = *(const ulonglong2*)(Wqs + k * OUTD + 4 * cg);
            ulonglong2 b1v = *(const ulonglong2*)(Wqs + k * OUTD + 64 + 4 * cg);
            u64 av0 = bcast2(((const float*)&a40)[kk]);
            u64 av1 = bcast2(((const float*)&a41)[kk]);
            acc[0][0] = f2fma(av0, b0.x,  acc[0][0]);
            acc[0][1] = f2fma(av0, b0.y,  acc[0][1]);
            acc[0][2] = f2fma(av0, b1v.x, acc[0][2]);
            acc[0][3] = f2fma(av0, b1v.y, acc[0][3]);
            acc[1][0] = f2fma(av1, b0.x,  acc[1][0]);
            acc[1][1] = f2fma(av1, b0.y,  acc[1][1]);
            acc[1][2] = f2fma(av1, b1v.x, acc[1][2]);
            acc[1][3] = f2fma(av1, b1v.y, acc[1][3]);
        }
    }

    float4 bv0 = *(const float4*)(bq + 4 * cg);
    float4 bv1 = *(const float4*)(bq + 64 + 4 * cg);
    const float* bb0 = (const float*)&bv0;
    const float* bb1 = (const float*)&bv1;

#pragma unroll
    for (int r = 0; r < 2; r++) {
        const int n = n0 + r;
        float4 r0 = make_float4(0.f, 0.f, 0.f, 0.f);
        float4 r1 = make_float4(0.f, 0.f, 0.f, 0.f);
#pragma unroll
        for (int d = 0; d < DD; d++) {
            int e = eixs[n * DD + d];
            float4 v0 = *(const float4*)(g_redge2 + (size_t)e * OUTD + 4 * cg);
            float4 v1 = *(const float4*)(g_redge2 + (size_t)e * OUTD + 64 + 4 * cg);
            r0.x += v0.x; r0.y += v0.y; r0.z += v0.z; r0.w += v0.w;
            r1.x += v1.x; r1.y += v1.y; r1.z += v1.z; r1.w += v1.w;
        }
        float o[8];
        upk2(acc[r][0], o[0], o[1]); upk2(acc[r][1], o[2], o[3]);
        upk2(acc[r][2], o[4], o[5]); upk2(acc[r][3], o[6], o[7]);
        const float* rr0 = (const float*)&r0;
        const float* rr1 = (const float*)&r1;
        float4 w0, w1v;
        w0.x = fmaxf((o[0] + degf * bb0[0] + rr0[0]) * invdeg, 0.f);
        w0.y = fmaxf((o[1] + degf * bb0[1] + rr0[1]) * invdeg, 0.f);
        w0.z = fmaxf((o[2] + degf * bb0[2] + rr0[2]) * invdeg, 0.f);
        w0.w = fmaxf((o[3] + degf * bb0[3] + rr0[3]) * invdeg, 0.f);
        w1v.x = fmaxf((o[4] + degf * bb1[0] + rr1[0]) * invdeg, 0.f);
        w1v.y = fmaxf((o[5] + degf * bb1[1] + rr1[1]) * invdeg, 0.f);
        w1v.z = fmaxf((o[6] + degf * bb1[2] + rr1[2]) * invdeg, 0.f);
        w1v.w = fmaxf((o[7] + degf * bb1[3] + rr1[3]) * invdeg, 0.f);
        *(float4*)(out + (size_t)(nb + n) * OUTD + 4 * cg)      = w0;
        *(float4*)(out + (size_t)(nb + n) * OUTD + 64 + 4 * cg) = w1v;
    }
}

// =====================================================================
extern "C" void kernel_launch(void* const* d_in, const int* in_sizes, int n_in,
                              void* d_out, int out_size)
{
    const float* X  = (const float*)d_in[0];
    const float* Wp = (const float*)d_in[1];
    const float* bp = (const float*)d_in[2];
    const float* Wq = (const float*)d_in[3];
    const float* bq = (const float*)d_in[4];
    const float* W1 = (const float*)d_in[5];
    const float* b1 = (const float*)d_in[6];
    const float* W2 = (const float*)d_in[7];
    const float* b2 = (const float*)d_in[8];
    const int*   en = (const int*)d_in[9];

    const int N  = in_sizes[0] / FEAT;
    const int EK = in_sizes[9];
    const int E  = EK / KK;
    const int deg = EK / N;
    const float num = powf((float)deg, 1.0f / (float)KK);
    const float C   = num * (1.0f / 6.0f);
    const int perm_edges = N / KK;

    cudaFuncSetAttribute(node_mlp_kernel,
                         cudaFuncAttributeMaxDynamicSharedMemorySize, SMEM1);

    node_mlp_kernel<<<N / 32, 256, SMEM1>>>(X, Wp, bp, W1, b1, W2, b2, num);
    edge_kernel<<<E / 8, 256>>>(en, C, perm_edges);
    out_kernel<<<N / 32, 256>>>(Wq, bq, (float*)d_out, (float)deg, 1.0f / (float)deg);
}

// round 10
// speedup vs baseline: 1.5599x; 1.0820x over previous
#include <cuda_runtime.h>
#include <math.h>

#define NN   100000
#define EE   200000
#define KK   4
#define DD   8
#define FEAT 256
#define RANK 64
#define HID  512
#define OUTD 128

// ---------------- scratch (static device arrays; no allocation) ----------------
__device__ float g_scaled[(size_t)NN * RANK];
__device__ float g_emb2[(size_t)NN * OUTD];
__device__ float g_term[(size_t)NN * DD * RANK];
__device__ int   g_eidx[(size_t)NN * DD];
__device__ float g_redge2[(size_t)EE * OUTD];

// ---------------- packed f32x2 helpers ----------------
typedef unsigned long long u64;

__device__ __forceinline__ u64 bcast2(float a) {
    u64 r; asm("mov.b64 %0, {%1, %1};" : "=l"(r) : "f"(a)); return r;
}
__device__ __forceinline__ void upk2(u64 p, float& a, float& b) {
    asm("mov.b64 {%0, %1}, %2;" : "=f"(a), "=f"(b) : "l"(p));
}
__device__ __forceinline__ u64 f2fma(u64 a, u64 b, u64 c) {
    u64 d; asm("fma.rn.f32x2 %0, %1, %2, %3;" : "=l"(d) : "l"(a), "l"(b), "l"(c)); return d;
}

// ---------------- cp.async helpers ----------------
__device__ __forceinline__ unsigned sm_u32(const void* p) {
    return (unsigned)__cvta_generic_to_shared(p);
}
__device__ __forceinline__ void cpa16(unsigned dst, const float4* src) {
    asm volatile("cp.async.ca.shared.global [%0], [%1], 16;" :: "r"(dst), "l"(src));
}
__device__ __forceinline__ void cpa_commit() {
    asm volatile("cp.async.commit_group;");
}
__device__ __forceinline__ void cpa_wait0() {
    asm volatile("cp.async.wait_group 0;");
}

// =====================================================================
// Kernel 1: fused node MLP. 32 nodes/CTA, 256 threads, 2 CTAs/SM.
// cp.async double-buffered weight staging (no staging registers).
// Phase 2 register blocking: 16 rows x 4 cols per thread.
// smem = Xs 32KB + Bigs 64KB (W1 ping/pong -> H) + Buf 16KB (Wp/W2 ping/pong)
// =====================================================================
#define SMEM1 ((32*FEAT + 32*HID + 32*OUTD) * 4)

__global__ __launch_bounds__(256, 2) void node_mlp_kernel(
    const float* __restrict__ X,
    const float* __restrict__ Wp, const float* __restrict__ bp,
    const float* __restrict__ W1, const float* __restrict__ b1,
    const float* __restrict__ W2, const float* __restrict__ b2,
    float num)
{
    extern __shared__ float sm[];
    float* Xs   = sm;                    // [32][256]
    float* Bigs = sm + 32 * FEAT;        // [32][512]
    float* Buf  = Bigs + 32 * HID;       // [32][128]
    const int t  = threadIdx.x;
    const int nb = blockIdx.x * 32;

    {
        const float4* src = (const float4*)(X + (size_t)nb * FEAT);
        float4* dst = (float4*)Xs;
#pragma unroll
        for (int i = 0; i < 8; i++) dst[t + i * 256] = src[t + i * 256];
    }

    // ---------------- Phase 1: emb1 = num*(X@Wp + bp) -> g_scaled ----------------
    // chunk = 32 k x 64 cols = 8KB; Buf holds 2 x 8KB ping/pong.
    {
        const int row = t >> 3;
        const int g   = t & 7;
        const unsigned bufA = sm_u32(Buf);
        const unsigned bufB = bufA + 32 * RANK * 4;
        {   // preload chunk 0 -> A
            const float4* src = (const float4*)Wp;
            cpa16(bufA + t * 16,            src + t);
            cpa16(bufA + (t + 256) * 16,    src + t + 256);
            cpa_commit(); cpa_wait0();
        }
        __syncthreads();   // also covers Xs

        u64 acc[4] = {0, 0, 0, 0};
        for (int c = 0; c < 8; c++) {
            if (c < 7) {
                const float4* src = (const float4*)(Wp + (size_t)(c + 1) * 32 * RANK);
                unsigned dst = ((c + 1) & 1) ? bufB : bufA;
                cpa16(dst + t * 16,         src + t);
                cpa16(dst + (t + 256) * 16, src + t + 256);
                cpa_commit();
            }
            const float* bc = (c & 1) ? (Buf + 32 * RANK) : Buf;
#pragma unroll
            for (int k4 = 0; k4 < 8; k4++) {
                float4 a4 = *(const float4*)(Xs + row * FEAT + c * 32 + k4 * 4);
                const float* ap = (const float*)&a4;
#pragma unroll
                for (int kk = 0; kk < 4; kk++) {
                    int k = k4 * 4 + kk;
                    ulonglong2 b0 = *(const ulonglong2*)(bc + k * RANK + 4 * g);
                    ulonglong2 b1v = *(const ulonglong2*)(bc + k * RANK + 32 + 4 * g);
                    u64 av = bcast2(ap[kk]);
                    acc[0] = f2fma(av, b0.x,  acc[0]);
                    acc[1] = f2fma(av, b0.y,  acc[1]);
                    acc[2] = f2fma(av, b1v.x, acc[2]);
                    acc[3] = f2fma(av, b1v.y, acc[3]);
                }
            }
            if (c < 7) cpa_wait0();
            __syncthreads();
        }
        float4 bv0 = *(const float4*)(bp + 4 * g);
        float4 bv1 = *(const float4*)(bp + 32 + 4 * g);
        float o[8];
        upk2(acc[0], o[0], o[1]); upk2(acc[1], o[2], o[3]);
        upk2(acc[2], o[4], o[5]); upk2(acc[3], o[6], o[7]);
        float4 w0 = make_float4(num * (o[0] + bv0.x), num * (o[1] + bv0.y),
                                num * (o[2] + bv0.z), num * (o[3] + bv0.w));
        float4 w1v = make_float4(num * (o[4] + bv1.x), num * (o[5] + bv1.y),
                                 num * (o[6] + bv1.z), num * (o[7] + bv1.w));
        *(float4*)(g_scaled + (size_t)(nb + row) * RANK + 4 * g)      = w0;
        *(float4*)(g_scaled + (size_t)(nb + row) * RANK + 32 + 4 * g) = w1v;
    }

    // ---------------- Phase 2: H = relu(X@W1 + b1) -> Bigs ----------------
    // thread: 16 rows (rg = t>>7), 4 contiguous cols (4*cg, cg = t&127).
    // W1 staged in Bigs as 2 x [16][512] ping/pong via cp.async; chunks of 16 k.
    {
        const int rg = t >> 7;          // 0..1
        const int cg = t & 127;         // 0..127
        const int r0 = rg * 16;
        float* BA = Bigs;
        float* BB = Bigs + 16 * HID;
        const unsigned baA = sm_u32(BA);
        const unsigned baB = sm_u32(BB);
        {   // preload chunk 0 -> A
            const float4* src = (const float4*)W1;
#pragma unroll
            for (int i = 0; i < 8; i++) cpa16(baA + (t + i * 256) * 16, src + t + i * 256);
            cpa_commit(); cpa_wait0();
        }
        __syncthreads();

        u64 acc[16][2];
#pragma unroll
        for (int i = 0; i < 16; i++) { acc[i][0] = 0; acc[i][1] = 0; }

        for (int c = 0; c < 16; c++) {
            if (c < 15) {
                const float4* src = (const float4*)(W1 + (size_t)(c + 1) * 16 * HID);
                unsigned dst = ((c + 1) & 1) ? baB : baA;
#pragma unroll
                for (int i = 0; i < 8; i++) cpa16(dst + (t + i * 256) * 16, src + t + i * 256);
                cpa_commit();
            }
            const float* bc = (c & 1) ? BB : BA;
#pragma unroll
            for (int k4 = 0; k4 < 4; k4++) {
                ulonglong2 B4[4];
#pragma unroll
                for (int kk = 0; kk < 4; kk++)
                    B4[kk] = *(const ulonglong2*)(bc + (k4 * 4 + kk) * HID + 4 * cg);
#pragma unroll
                for (int r = 0; r < 16; r++) {
                    float4 a4 = *(const float4*)(Xs + (r0 + r) * FEAT + c * 16 + k4 * 4);
                    const float* ap = (const float*)&a4;
#pragma unroll
                    for (int kk = 0; kk < 4; kk++) {
                        u64 av = bcast2(ap[kk]);
                        acc[r][0] = f2fma(av, B4[kk].x, acc[r][0]);
                        acc[r][1] = f2fma(av, B4[kk].y, acc[r][1]);
                    }
                }
            }
            if (c < 15) cpa_wait0();
            __syncthreads();
        }

        // write H (relu) into Bigs; all reads of W1 buffers done (last sync above)
        float4 bv = *(const float4*)(b1 + 4 * cg);
#pragma unroll
        for (int r = 0; r < 16; r++) {
            float o0, o1, o2, o3;
            upk2(acc[r][0], o0, o1);
            upk2(acc[r][1], o2, o3);
            float4 h;
            h.x = fmaxf(o0 + bv.x, 0.f);
            h.y = fmaxf(o1 + bv.y, 0.f);
            h.z = fmaxf(o2 + bv.z, 0.f);
            h.w = fmaxf(o3 + bv.w, 0.f);
            *(float4*)(Bigs + (r0 + r) * HID + 4 * cg) = h;
        }
        __syncthreads();
    }

    // ---------------- Phase 3: emb2 = H@W2 + b2 -> g_emb2 ----------------
    // thread: 2 rows (n0 = (t>>4)*2), cols {4cg..+3, 64+4cg..+3}, cg = t&15.
    // W2 staged in Buf as 2 x [16][128] ping/pong via cp.async; chunks of 16 k.
    {
        const int n0 = (t >> 4) * 2;
        const int cg = t & 15;
        float* CA = Buf;
        float* CB = Buf + 16 * OUTD;
        const unsigned caA = sm_u32(CA);
        const unsigned caB = sm_u32(CB);
        {   // preload chunk 0 -> A
            const float4* src = (const float4*)W2;
            cpa16(caA + t * 16,         src + t);
            cpa16(caA + (t + 256) * 16, src + t + 256);
            cpa_commit(); cpa_wait0();
        }
        __syncthreads();

        u64 acc[2][4];
#pragma unroll
        for (int r = 0; r < 2; r++)
#pragma unroll
            for (int j = 0; j < 4; j++) acc[r][j] = 0;

        for (int c = 0; c < 32; c++) {
            if (c < 31) {
                const float4* src = (const float4*)(W2 + (size_t)(c + 1) * 16 * OUTD);
                unsigned dst = ((c + 1) & 1) ? caB : caA;
                cpa16(dst + t * 16,         src + t);
                cpa16(dst + (t + 256) * 16, src + t + 256);
                cpa_commit();
            }
            const float* bc = (c & 1) ? CB : CA;
#pragma unroll
            for (int k4 = 0; k4 < 4; k4++) {
                float4 a40 = *(const float4*)(Bigs + n0 * HID + c * 16 + k4 * 4);
                float4 a41 = *(const float4*)(Bigs + (n0 + 1) * HID + c * 16 + k4 * 4);
#pragma unroll
                for (int kk = 0; kk < 4; kk++) {
                    int k = k4 * 4 + kk;
                    ulonglong2 b0 = *(const ulonglong2*)(bc + k * OUTD + 4 * cg);
                    ulonglong2 b1v = *(const ulonglong2*)(bc + k * OUTD + 64 + 4 * cg);
                    u64 av0 = bcast2(((const float*)&a40)[kk]);
                    u64 av1 = bcast2(((const float*)&a41)[kk]);
                    acc[0][0] = f2fma(av0, b0.x,  acc[0][0]);
                    acc[0][1] = f2fma(av0, b0.y,  acc[0][1]);
                    acc[0][2] = f2fma(av0, b1v.x, acc[0][2]);
                    acc[0][3] = f2fma(av0, b1v.y, acc[0][3]);
                    acc[1][0] = f2fma(av1, b0.x,  acc[1][0]);
                    acc[1][1] = f2fma(av1, b0.y,  acc[1][1]);
                    acc[1][2] = f2fma(av1, b1v.x, acc[1][2]);
                    acc[1][3] = f2fma(av1, b1v.y, acc[1][3]);
                }
            }
            if (c < 31) cpa_wait0();
            __syncthreads();
        }

        float4 bv0 = *(const float4*)(b2 + 4 * cg);
        float4 bv1 = *(const float4*)(b2 + 64 + 4 * cg);
        const float* bb0 = (const float*)&bv0;
        const float* bb1 = (const float*)&bv1;
#pragma unroll
        for (int r = 0; r < 2; r++) {
            float o[8];
            upk2(acc[r][0], o[0], o[1]); upk2(acc[r][1], o[2], o[3]);
            upk2(acc[r][2], o[4], o[5]); upk2(acc[r][3], o[6], o[7]);
            float4 w0 = make_float4(o[0] + bb0[0], o[1] + bb0[1],
                                    o[2] + bb0[2], o[3] + bb0[3]);
            float4 w1v = make_float4(o[4] + bb1[0], o[5] + bb1[1],
                                     o[6] + bb1[2], o[7] + bb1[3]);
            *(float4*)(g_emb2 + (size_t)(nb + n0 + r) * OUTD + 4 * cg)      = w0;
            *(float4*)(g_emb2 + (size_t)(nb + n0 + r) * OUTD + 64 + 4 * cg) = w1v;
        }
    }
}

// =====================================================================
// Kernel 2: per-edge (unchanged).
// =====================================================================
__global__ __launch_bounds__(256) void edge_kernel(
    const int* __restrict__ en, float C, int perm_edges)
{
    const int lane = threadIdx.x & 31;
    const int e    = blockIdx.x * 8 + (threadIdx.x >> 5);

    int myn = 0;
    if (lane < 4) myn = en[e * 4 + lane];
    const unsigned m = 0xffffffffu;
    int n0 = __shfl_sync(m, myn, 0);
    int n1 = __shfl_sync(m, myn, 1);
    int n2 = __shfl_sync(m, myn, 2);
    int n3 = __shfl_sync(m, myn, 3);

    float2 g0 = *(const float2*)(g_scaled + (size_t)n0 * RANK + lane * 2);
    float2 g1 = *(const float2*)(g_scaled + (size_t)n1 * RANK + lane * 2);
    float2 g2 = *(const float2*)(g_scaled + (size_t)n2 * RANK + lane * 2);
    float2 g3 = *(const float2*)(g_scaled + (size_t)n3 * RANK + lane * 2);

    float2 a, b;
    a.x = g0.x * g1.x; a.y = g0.y * g1.y;
    b.x = g2.x * g3.x; b.y = g2.y * g3.y;
    float2 t0, t1, t2, t3;
    t0.x = tanhf(C * (g1.x * b.x)); t0.y = tanhf(C * (g1.y * b.y));
    t1.x = tanhf(C * (g0.x * b.x)); t1.y = tanhf(C * (g0.y * b.y));
    t2.x = tanhf(C * (a.x * g3.x)); t2.y = tanhf(C * (a.y * g3.y));
    t3.x = tanhf(C * (a.x * g2.x)); t3.y = tanhf(C * (a.y * g2.y));

    const int d = e / perm_edges;
    *(float2*)(g_term + ((size_t)n0 * DD + d) * RANK + lane * 2) = t0;
    *(float2*)(g_term + ((size_t)n1 * DD + d) * RANK + lane * 2) = t1;
    *(float2*)(g_term + ((size_t)n2 * DD + d) * RANK + lane * 2) = t2;
    *(float2*)(g_term + ((size_t)n3 * DD + d) * RANK + lane * 2) = t3;
    if (lane < 4) g_eidx[(size_t)myn * DD + d] = e;

    float4 s = make_float4(0.f, 0.f, 0.f, 0.f);
    float4 v;
    v = *(const float4*)(g_emb2 + (size_t)n0 * OUTD + lane * 4);
    s.x += v.x; s.y += v.y; s.z += v.z; s.w += v.w;
    v = *(const float4*)(g_emb2 + (size_t)n1 * OUTD + lane * 4);
    s.x += v.x; s.y += v.y; s.z += v.z; s.w += v.w;
    v = *(const float4*)(g_emb2 + (size_t)n2 * OUTD + lane * 4);
    s.x += v.x; s.y += v.y; s.z += v.z; s.w += v.w;
    v = *(const float4*)(g_emb2 + (size_t)n3 * OUTD + lane * 4);
    s.x += v.x; s.y += v.y; s.z += v.z; s.w += v.w;
    s.x = fmaxf(s.x, 0.f); s.y = fmaxf(s.y, 0.f);
    s.z = fmaxf(s.z, 0.f); s.w = fmaxf(s.w, 0.f);
    *(float4*)(g_redge2 + (size_t)e * OUTD + lane * 4) = s;
}

// =====================================================================
// Kernel 3: per-node output (unchanged).
// =====================================================================
__global__ __launch_bounds__(256) void out_kernel(
    const float* __restrict__ Wq, const float* __restrict__ bq,
    float* __restrict__ out, float degf, float invdeg)
{
    __shared__ float tsums[32 * RANK];
    __shared__ float Wqs[RANK * OUTD];
    __shared__ int   eixs[32 * DD];
    const int t  = threadIdx.x;
    const int nb = blockIdx.x * 32;

    {
        const float4* ws = (const float4*)Wq;
        float4* wd = (float4*)Wqs;
#pragma unroll
        for (int i = 0; i < 8; i++) wd[t + i * 256] = ws[t + i * 256];
    }
    eixs[t] = g_eidx[(size_t)nb * DD + t];

    {
        const int n = t >> 3;
        const int p = (t & 7) * 8;
        const float* src = g_term + (size_t)(nb + n) * DD * RANK + p;
        float4 s0 = make_float4(0.f, 0.f, 0.f, 0.f);
        float4 s1 = make_float4(0.f, 0.f, 0.f, 0.f);
#pragma unroll
        for (int d = 0; d < DD; d++) {
            float4 v0 = *(const float4*)(src + d * RANK);
            float4 v1 = *(const float4*)(src + d * RANK + 4);
            s0.x += v0.x; s0.y += v0.y; s0.z += v0.z; s0.w += v0.w;
            s1.x += v1.x; s1.y += v1.y; s1.z += v1.z; s1.w += v1.w;
        }
        *(float4*)(tsums + n * RANK + p)     = s0;
        *(float4*)(tsums + n * RANK + p + 4) = s1;
    }
    __syncthreads();

    const int n0 = (t >> 4) * 2;
    const int cg = t & 15;
    u64 acc[2][4];
#pragma unroll
    for (int r = 0; r < 2; r++)
#pragma unroll
        for (int j = 0; j < 4; j++) acc[r][j] = 0;

#pragma unroll
    for (int k4 = 0; k4 < RANK / 4; k4++) {
        float4 a40 = *(const float4*)(tsums + n0 * RANK + k4 * 4);
        float4 a41 = *(const float4*)(tsums + (n0 + 1) * RANK + k4 * 4);
#pragma unroll
        for (int kk = 0; kk < 4; kk++) {
            int k = k4 * 4 + kk;
            ulonglong2 b0 = *(const ulonglong2*)(Wqs + k * OUTD + 4 * cg);
            ulonglong2 b1v = *(const ulonglong2*)(Wqs + k * OUTD + 64 + 4 * cg);
            u64 av0 = bcast2(((const float*)&a40)[kk]);
            u64 av1 = bcast2(((const float*)&a41)[kk]);
            acc[0][0] = f2fma(av0, b0.x,  acc[0][0]);
            acc[0][1] = f2fma(av0, b0.y,  acc[0][1]);
            acc[0][2] = f2fma(av0, b1v.x, acc[0][2]);
            acc[0][3] = f2fma(av0, b1v.y, acc[0][3]);
            acc[1][0] = f2fma(av1, b0.x,  acc[1][0]);
            acc[1][1] = f2fma(av1, b0.y,  acc[1][1]);
            acc[1][2] = f2fma(av1, b1v.x, acc[1][2]);
            acc[1][3] = f2fma(av1, b1v.y, acc[1][3]);
        }
    }

    float4 bv0 = *(const float4*)(bq + 4 * cg);
    float4 bv1 = *(const float4*)(bq + 64 + 4 * cg);
    const float* bb0 = (const float*)&bv0;
    const float* bb1 = (const float*)&bv1;

#pragma unroll
    for (int r = 0; r < 2; r++) {
        const int n = n0 + r;
        float4 r0 = make_float4(0.f, 0.f, 0.f, 0.f);
        float4 r1 = make_float4(0.f, 0.f, 0.f, 0.f);
#pragma unroll
        for (int d = 0; d < DD; d++) {
            int e = eixs[n * DD + d];
            float4 v0 = *(const float4*)(g_redge2 + (size_t)e * OUTD + 4 * cg);
            float4 v1 = *(const float4*)(g_redge2 + (size_t)e * OUTD + 64 + 4 * cg);
            r0.x += v0.x; r0.y += v0.y; r0.z += v0.z; r0.w += v0.w;
            r1.x += v1.x; r1.y += v1.y; r1.z += v1.z; r1.w += v1.w;
        }
        float o[8];
        upk2(acc[r][0], o[0], o[1]); upk2(acc[r][1], o[2], o[3]);
        upk2(acc[r][2], o[4], o[5]); upk2(acc[r][3], o[6], o[7]);
        const float* rr0 = (const float*)&r0;
        const float* rr1 = (const float*)&r1;
        float4 w0, w1v;
        w0.x = fmaxf((o[0] + degf * bb0[0] + rr0[0]) * invdeg, 0.f);
        w0.y = fmaxf((o[1] + degf * bb0[1] + rr0[1]) * invdeg, 0.f);
        w0.z = fmaxf((o[2] + degf * bb0[2] + rr0[2]) * invdeg, 0.f);
        w0.w = fmaxf((o[3] + degf * bb0[3] + rr0[3]) * invdeg, 0.f);
        w1v.x = fmaxf((o[4] + degf * bb1[0] + rr1[0]) * invdeg, 0.f);
        w1v.y = fmaxf((o[5] + degf * bb1[1] + rr1[1]) * invdeg, 0.f);
        w1v.z = fmaxf((o[6] + degf * bb1[2] + rr1[2]) * invdeg, 0.f);
        w1v.w = fmaxf((o[7] + degf * bb1[3] + rr1[3]) * invdeg, 0.f);
        *(float4*)(out + (size_t)(nb + n) * OUTD + 4 * cg)      = w0;
        *(float4*)(out + (size_t)(nb + n) * OUTD + 64 + 4 * cg) = w1v;
    }
}

// =====================================================================
extern "C" void kernel_launch(void* const* d_in, const int* in_sizes, int n_in,
                              void* d_out, int out_size)
{
    const float* X  = (const float*)d_in[0];
    const float* Wp = (const float*)d_in[1];
    const float* bp = (const float*)d_in[2];
    const float* Wq = (const float*)d_in[3];
    const float* bq = (const float*)d_in[4];
    const float* W1 = (const float*)d_in[5];
    const float* b1 = (const float*)d_in[6];
    const float* W2 = (const float*)d_in[7];
    const float* b2 = (const float*)d_in[8];
    const int*   en = (const int*)d_in[9];

    const int N  = in_sizes[0] / FEAT;
    const int EK = in_sizes[9];
    const int E  = EK / KK;
    const int deg = EK / N;
    const float num = powf((float)deg, 1.0f / (float)KK);
    const float C   = num * (1.0f / 6.0f);
    const int perm_edges = N / KK;

    cudaFuncSetAttribute(node_mlp_kernel,
                         cudaFuncAttributeMaxDynamicSharedMemorySize, SMEM1);

    node_mlp_kernel<<<N / 32, 256, SMEM1>>>(X, Wp, bp, W1, b1, W2, b2, num);
    edge_kernel<<<E / 8, 256>>>(en, C, perm_edges);
    out_kernel<<<N / 32, 256>>>(Wq, bq, (float*)d_out, (float)deg, 1.0f / (float)deg);
}

// round 11
// speedup vs baseline: 1.5606x; 1.0004x over previous
#include <cuda_runtime.h>
#include <math.h>

#define NN   100000
#define EE   200000
#define KK   4
#define DD   8
#define FEAT 256
#define RANK 64
#define HID  512
#define OUTD 128

// ---------------- scratch (static device arrays; no allocation) ----------------
__device__ float g_scaled[(size_t)NN * RANK];
__device__ float g_emb2[(size_t)NN * OUTD];
__device__ float g_term[(size_t)NN * DD * RANK];
__device__ int   g_eidx[(size_t)NN * DD];
__device__ float g_redge2[(size_t)EE * OUTD];

// ---------------- packed f32x2 helpers ----------------
typedef unsigned long long u64;

__device__ __forceinline__ u64 bcast2(float a) {
    u64 r; asm("mov.b64 %0, {%1, %1};" : "=l"(r) : "f"(a)); return r;
}
__device__ __forceinline__ void upk2(u64 p, float& a, float& b) {
    asm("mov.b64 {%0, %1}, %2;" : "=f"(a), "=f"(b) : "l"(p));
}
__device__ __forceinline__ u64 f2fma(u64 a, u64 b, u64 c) {
    u64 d; asm("fma.rn.f32x2 %0, %1, %2, %3;" : "=l"(d) : "l"(a), "l"(b), "l"(c)); return d;
}

// ---------------- cp.async helpers ----------------
__device__ __forceinline__ unsigned sm_u32(const void* p) {
    return (unsigned)__cvta_generic_to_shared(p);
}
__device__ __forceinline__ void cpa16(unsigned dst, const float4* src) {
    asm volatile("cp.async.ca.shared.global [%0], [%1], 16;" :: "r"(dst), "l"(src));
}
__device__ __forceinline__ void cpa_commit() {
    asm volatile("cp.async.commit_group;");
}
__device__ __forceinline__ void cpa_wait0() {
    asm volatile("cp.async.wait_group 0;");
}

// =====================================================================
// Kernel 1: fused node MLP. 32 nodes/CTA, 256 threads, 2 CTAs/SM.
// cp.async double-buffered weight staging (no staging registers).
// Phase 2 register blocking: 16 rows x 4 cols per thread.
// smem = Xs 32KB + Bigs 64KB (W1 ping/pong -> H) + Buf 16KB (Wp/W2 ping/pong)
// =====================================================================
#define SMEM1 ((32*FEAT + 32*HID + 32*OUTD) * 4)

__global__ __launch_bounds__(256, 2) void node_mlp_kernel(
    const float* __restrict__ X,
    const float* __restrict__ Wp, const float* __restrict__ bp,
    const float* __restrict__ W1, const float* __restrict__ b1,
    const float* __restrict__ W2, const float* __restrict__ b2,
    float num)
{
    extern __shared__ float sm[];
    float* Xs   = sm;                    // [32][256]
    float* Bigs = sm + 32 * FEAT;        // [32][512]
    float* Buf  = Bigs + 32 * HID;       // [32][128]
    const int t  = threadIdx.x;
    const int nb = blockIdx.x * 32;

    {
        const float4* src = (const float4*)(X + (size_t)nb * FEAT);
        float4* dst = (float4*)Xs;
#pragma unroll
        for (int i = 0; i < 8; i++) dst[t + i * 256] = src[t + i * 256];
    }

    // ---------------- Phase 1: emb1 = num*(X@Wp + bp) -> g_scaled ----------------
    // chunk = 32 k x 64 cols = 8KB; Buf holds 2 x 8KB ping/pong.
    {
        const int row = t >> 3;
        const int g   = t & 7;
        const unsigned bufA = sm_u32(Buf);
        const unsigned bufB = bufA + 32 * RANK * 4;
        {   // preload chunk 0 -> A
            const float4* src = (const float4*)Wp;
            cpa16(bufA + t * 16,            src + t);
            cpa16(bufA + (t + 256) * 16,    src + t + 256);
            cpa_commit(); cpa_wait0();
        }
        __syncthreads();   // also covers Xs

        u64 acc[4] = {0, 0, 0, 0};
        for (int c = 0; c < 8; c++) {
            if (c < 7) {
                const float4* src = (const float4*)(Wp + (size_t)(c + 1) * 32 * RANK);
                unsigned dst = ((c + 1) & 1) ? bufB : bufA;
                cpa16(dst + t * 16,         src + t);
                cpa16(dst + (t + 256) * 16, src + t + 256);
                cpa_commit();
            }
            const float* bc = (c & 1) ? (Buf + 32 * RANK) : Buf;
#pragma unroll
            for (int k4 = 0; k4 < 8; k4++) {
                float4 a4 = *(const float4*)(Xs + row * FEAT + c * 32 + k4 * 4);
                const float* ap = (const float*)&a4;
#pragma unroll
                for (int kk = 0; kk < 4; kk++) {
                    int k = k4 * 4 + kk;
                    ulonglong2 b0 = *(const ulonglong2*)(bc + k * RANK + 4 * g);
                    ulonglong2 b1v = *(const ulonglong2*)(bc + k * RANK + 32 + 4 * g);
                    u64 av = bcast2(ap[kk]);
                    acc[0] = f2fma(av, b0.x,  acc[0]);
                    acc[1] = f2fma(av, b0.y,  acc[1]);
                    acc[2] = f2fma(av, b1v.x, acc[2]);
                    acc[3] = f2fma(av, b1v.y, acc[3]);
                }
            }
            if (c < 7) cpa_wait0();
            __syncthreads();
        }
        float4 bv0 = *(const float4*)(bp + 4 * g);
        float4 bv1 = *(const float4*)(bp + 32 + 4 * g);
        float o[8];
        upk2(acc[0], o[0], o[1]); upk2(acc[1], o[2], o[3]);
        upk2(acc[2], o[4], o[5]); upk2(acc[3], o[6], o[7]);
        float4 w0 = make_float4(num * (o[0] + bv0.x), num * (o[1] + bv0.y),
                                num * (o[2] + bv0.z), num * (o[3] + bv0.w));
        float4 w1v = make_float4(num * (o[4] + bv1.x), num * (o[5] + bv1.y),
                                 num * (o[6] + bv1.z), num * (o[7] + bv1.w));
        *(float4*)(g_scaled + (size_t)(nb + row) * RANK + 4 * g)      = w0;
        *(float4*)(g_scaled + (size_t)(nb + row) * RANK + 32 + 4 * g) = w1v;
    }

    // ---------------- Phase 2: H = relu(X@W1 + b1) -> Bigs ----------------
    // thread: 16 rows (rg = t>>7), 4 contiguous cols (4*cg, cg = t&127).
    // W1 staged in Bigs as 2 x [16][512] ping/pong via cp.async; chunks of 16 k.
    {
        const int rg = t >> 7;          // 0..1
        const int cg = t & 127;         // 0..127
        const int r0 = rg * 16;
        float* BA = Bigs;
        float* BB = Bigs + 16 * HID;
        const unsigned baA = sm_u32(BA);
        const unsigned baB = sm_u32(BB);
        {   // preload chunk 0 -> A
            const float4* src = (const float4*)W1;
#pragma unroll
            for (int i = 0; i < 8; i++) cpa16(baA + (t + i * 256) * 16, src + t + i * 256);
            cpa_commit(); cpa_wait0();
        }
        __syncthreads();

        u64 acc[16][2];
#pragma unroll
        for (int i = 0; i < 16; i++) { acc[i][0] = 0; acc[i][1] = 0; }

        for (int c = 0; c < 16; c++) {
            if (c < 15) {
                const float4* src = (const float4*)(W1 + (size_t)(c + 1) * 16 * HID);
                unsigned dst = ((c + 1) & 1) ? baB : baA;
#pragma unroll
                for (int i = 0; i < 8; i++) cpa16(dst + (t + i * 256) * 16, src + t + i * 256);
                cpa_commit();
            }
            const float* bc = (c & 1) ? BB : BA;
#pragma unroll
            for (int k4 = 0; k4 < 4; k4++) {
                ulonglong2 B4[4];
#pragma unroll
                for (int kk = 0; kk < 4; kk++)
                    B4[kk] = *(const ulonglong2*)(bc + (k4 * 4 + kk) * HID + 4 * cg);
#pragma unroll
                for (int r = 0; r < 16; r++) {
                    float4 a4 = *(const float4*)(Xs + (r0 + r) * FEAT + c * 16 + k4 * 4);
                    const float* ap = (const float*)&a4;
#pragma unroll
                    for (int kk = 0; kk < 4; kk++) {
                        u64 av = bcast2(ap[kk]);
                        acc[r][0] = f2fma(av, B4[kk].x, acc[r][0]);
                        acc[r][1] = f2fma(av, B4[kk].y, acc[r][1]);
                    }
                }
            }
            if (c < 15) cpa_wait0();
            __syncthreads();
        }

        // write H (relu) into Bigs; all reads of W1 buffers done (last sync above)
        float4 bv = *(const float4*)(b1 + 4 * cg);
#pragma unroll
        for (int r = 0; r < 16; r++) {
            float o0, o1, o2, o3;
            upk2(acc[r][0], o0, o1);
            upk2(acc[r][1], o2, o3);
            float4 h;
            h.x = fmaxf(o0 + bv.x, 0.f);
            h.y = fmaxf(o1 + bv.y, 0.f);
            h.z = fmaxf(o2 + bv.z, 0.f);
            h.w = fmaxf(o3 + bv.w, 0.f);
            *(float4*)(Bigs + (r0 + r) * HID + 4 * cg) = h;
        }
        __syncthreads();
    }

    // ---------------- Phase 3: emb2 = H@W2 + b2 -> g_emb2 ----------------
    // thread: 2 rows (n0 = (t>>4)*2), cols {4cg..+3, 64+4cg..+3}, cg = t&15.
    // W2 staged in Buf as 2 x [16][128] ping/pong via cp.async; chunks of 16 k.
    {
        const int n0 = (t >> 4) * 2;
        const int cg = t & 15;
        float* CA = Buf;
        float* CB = Buf + 16 * OUTD;
        const unsigned caA = sm_u32(CA);
        const unsigned caB = sm_u32(CB);
        {   // preload chunk 0 -> A
            const float4* src = (const float4*)W2;
            cpa16(caA + t * 16,         src + t);
            cpa16(caA + (t + 256) * 16, src + t + 256);
            cpa_commit(); cpa_wait0();
        }
        __syncthreads();

        u64 acc[2][4];
#pragma unroll
        for (int r = 0; r < 2; r++)
#pragma unroll
            for (int j = 0; j < 4; j++) acc[r][j] = 0;

        for (int c = 0; c < 32; c++) {
            if (c < 31) {
                const float4* src = (const float4*)(W2 + (size_t)(c + 1) * 16 * OUTD);
                unsigned dst = ((c + 1) & 1) ? caB : caA;
                cpa16(dst + t * 16,         src + t);
                cpa16(dst + (t + 256) * 16, src + t + 256);
                cpa_commit();
            }
            const float* bc = (c & 1) ? CB : CA;
#pragma unroll
            for (int k4 = 0; k4 < 4; k4++) {
                float4 a40 = *(const float4*)(Bigs + n0 * HID + c * 16 + k4 * 4);
                float4 a41 = *(const float4*)(Bigs + (n0 + 1) * HID + c * 16 + k4 * 4);
#pragma unroll
                for (int kk = 0; kk < 4; kk++) {
                    int k = k4 * 4 + kk;
                    ulonglong2 b0 = *(const ulonglong2*)(bc + k * OUTD + 4 * cg);
                    ulonglong2 b1v = *(const ulonglong2*)(bc + k * OUTD + 64 + 4 * cg);
                    u64 av0 = bcast2(((const float*)&a40)[kk]);
                    u64 av1 = bcast2(((const float*)&a41)[kk]);
                    acc[0][0] = f2fma(av0, b0.x,  acc[0][0]);
                    acc[0][1] = f2fma(av0, b0.y,  acc[0][1]);
                    acc[0][2] = f2fma(av0, b1v.x, acc[0][2]);
                    acc[0][3] = f2fma(av0, b1v.y, acc[0][3]);
                    acc[1][0] = f2fma(av1, b0.x,  acc[1][0]);
                    acc[1][1] = f2fma(av1, b0.y,  acc[1][1]);
                    acc[1][2] = f2fma(av1, b1v.x, acc[1][2]);
                    acc[1][3] = f2fma(av1, b1v.y, acc[1][3]);
                }
            }
            if (c < 31) cpa_wait0();
            __syncthreads();
        }

        float4 bv0 = *(const float4*)(b2 + 4 * cg);
        float4 bv1 = *(const float4*)(b2 + 64 + 4 * cg);
        const float* bb0 = (const float*)&bv0;
        const float* bb1 = (const float*)&bv1;
#pragma unroll
        for (int r = 0; r < 2; r++) {
            float o[8];
            upk2(acc[r][0], o[0], o[1]); upk2(acc[r][1], o[2], o[3]);
            upk2(acc[r][2], o[4], o[5]); upk2(acc[r][3], o[6], o[7]);
            float4 w0 = make_float4(o[0] + bb0[0], o[1] + bb0[1],
                                    o[2] + bb0[2], o[3] + bb0[3]);
            float4 w1v = make_float4(o[4] + bb1[0], o[5] + bb1[1],
                                     o[6] + bb1[2], o[7] + bb1[3]);
            *(float4*)(g_emb2 + (size_t)(nb + n0 + r) * OUTD + 4 * cg)      = w0;
            *(float4*)(g_emb2 + (size_t)(nb + n0 + r) * OUTD + 64 + 4 * cg) = w1v;
        }
    }
}

// =====================================================================
// Kernel 2: per-edge (unchanged).
// =====================================================================
__global__ __launch_bounds__(256) void edge_kernel(
    const int* __restrict__ en, float C, int perm_edges)
{
    const int lane = threadIdx.x & 31;
    const int e    = blockIdx.x * 8 + (threadIdx.x >> 5);

    int myn = 0;
    if (lane < 4) myn = en[e * 4 + lane];
    const unsigned m = 0xffffffffu;
    int n0 = __shfl_sync(m, myn, 0);
    int n1 = __shfl_sync(m, myn, 1);
    int n2 = __shfl_sync(m, myn, 2);
    int n3 = __shfl_sync(m, myn, 3);

    float2 g0 = *(const float2*)(g_scaled + (size_t)n0 * RANK + lane * 2);
    float2 g1 = *(const float2*)(g_scaled + (size_t)n1 * RANK + lane * 2);
    float2 g2 = *(const float2*)(g_scaled + (size_t)n2 * RANK + lane * 2);
    float2 g3 = *(const float2*)(g_scaled + (size_t)n3 * RANK + lane * 2);

    float2 a, b;
    a.x = g0.x * g1.x; a.y = g0.y * g1.y;
    b.x = g2.x * g3.x; b.y = g2.y * g3.y;
    float2 t0, t1, t2, t3;
    t0.x = tanhf(C * (g1.x * b.x)); t0.y = tanhf(C * (g1.y * b.y));
    t1.x = tanhf(C * (g0.x * b.x)); t1.y = tanhf(C * (g0.y * b.y));
    t2.x = tanhf(C * (a.x * g3.x)); t2.y = tanhf(C * (a.y * g3.y));
    t3.x = tanhf(C * (a.x * g2.x)); t3.y = tanhf(C * (a.y * g2.y));

    const int d = e / perm_edges;
    *(float2*)(g_term + ((size_t)n0 * DD + d) * RANK + lane * 2) = t0;
    *(float2*)(g_term + ((size_t)n1 * DD + d) * RANK + lane * 2) = t1;
    *(float2*)(g_term + ((size_t)n2 * DD + d) * RANK + lane * 2) = t2;
    *(float2*)(g_term + ((size_t)n3 * DD + d) * RANK + lane * 2) = t3;
    if (lane < 4) g_eidx[(size_t)myn * DD + d] = e;

    float4 s = make_float4(0.f, 0.f, 0.f, 0.f);
    float4 v;
    v = *(const float4*)(g_emb2 + (size_t)n0 * OUTD + lane * 4);
    s.x += v.x; s.y += v.y; s.z += v.z; s.w += v.w;
    v = *(const float4*)(g_emb2 + (size_t)n1 * OUTD + lane * 4);
    s.x += v.x; s.y += v.y; s.z += v.z; s.w += v.w;
    v = *(const float4*)(g_emb2 + (size_t)n2 * OUTD + lane * 4);
    s.x += v.x; s.y += v.y; s.z += v.z; s.w += v.w;
    v = *(const float4*)(g_emb2 + (size_t)n3 * OUTD + lane * 4);
    s.x += v.x; s.y += v.y; s.z += v.z; s.w += v.w;
    s.x = fmaxf(s.x, 0.f); s.y = fmaxf(s.y, 0.f);
    s.z = fmaxf(s.z, 0.f); s.w = fmaxf(s.w, 0.f);
    *(float4*)(g_redge2 + (size_t)e * OUTD + lane * 4) = s;
}

// =====================================================================
// Kernel 3: per-node output (unchanged).
// =====================================================================
__global__ __launch_bounds__(256) void out_kernel(
    const float* __restrict__ Wq, const float* __restrict__ bq,
    float* __restrict__ out, float degf, float invdeg)
{
    __shared__ float tsums[32 * RANK];
    __shared__ float Wqs[RANK * OUTD];
    __shared__ int   eixs[32 * DD];
    const int t  = threadIdx.x;
    const int nb = blockIdx.x * 32;

    {
        const float4* ws = (const float4*)Wq;
        float4* wd = (float4*)Wqs;
#pragma unroll
        for (int i = 0; i < 8; i++) wd[t + i * 256] = ws[t + i * 256];
    }
    eixs[t] = g_eidx[(size_t)nb * DD + t];

    {
        const int n = t >> 3;
        const int p = (t & 7) * 8;
        const float* src = g_term + (size_t)(nb + n) * DD * RANK + p;
        float4 s0 = make_float4(0.f, 0.f, 0.f, 0.f);
        float4 s1 = make_float4(0.f, 0.f, 0.f, 0.f);
#pragma unroll
        for (int d = 0; d < DD; d++) {
            float4 v0 = *(const float4*)(src + d * RANK);
            float4 v1 = *(const float4*)(src + d * RANK + 4);
            s0.x += v0.x; s0.y += v0.y; s0.z += v0.z; s0.w += v0.w;
            s1.x += v1.x; s1.y += v1.y; s1.z += v1.z; s1.w += v1.w;
        }
        *(float4*)(tsums + n * RANK + p)     = s0;
        *(float4*)(tsums + n * RANK + p + 4) = s1;
    }
    __syncthreads();

    const int n0 = (t >> 4) * 2;
    const int cg = t & 15;
    u64 acc[2][4];
#pragma unroll
    for (int r = 0; r < 2; r++)
#pragma unroll
        for (int j = 0; j < 4; j++) acc[r][j] = 0;

#pragma unroll
    for (int k4 = 0; k4 < RANK / 4; k4++) {
        float4 a40 = *(const float4*)(tsums + n0 * RANK + k4 * 4);
        float4 a41 = *(const float4*)(tsums + (n0 + 1) * RANK + k4 * 4);
#pragma unroll
        for (int kk = 0; kk < 4; kk++) {
            int k = k4 * 4 + kk;
            ulonglong2 b0 = *(const ulonglong2*)(Wqs + k * OUTD + 4 * cg);
            ulonglong2 b1v = *(const ulonglong2*)(Wqs + k * OUTD + 64 + 4 * cg);
            u64 av0 = bcast2(((const float*)&a40)[kk]);
            u64 av1 = bcast2(((const float*)&a41)[kk]);
            acc[0][0] = f2fma(av0, b0.x,  acc[0][0]);
            acc[0][1] = f2fma(av0, b0.y,  acc[0][1]);
            acc[0][2] = f2fma(av0, b1v.x, acc[0][2]);
            acc[0][3] = f2fma(av0, b1v.y, acc[0][3]);
            acc[1][0] = f2fma(av1, b0.x,  acc[1][0]);
            acc[1][1] = f2fma(av1, b0.y,  acc[1][1]);
            acc[1][2] = f2fma(av1, b1v.x, acc[1][2]);
            acc[1][3] = f2fma(av1, b1v.y, acc[1][3]);
        }
    }

    float4 bv0 = *(const float4*)(bq + 4 * cg);
    float4 bv1 = *(const float4*)(bq + 64 + 4 * cg);
    const float* bb0 = (const float*)&bv0;
    const float* bb1 = (const float*)&bv1;

#pragma unroll
    for (int r = 0; r < 2; r++) {
        const int n = n0 + r;
        float4 r0 = make_float4(0.f, 0.f, 0.f, 0.f);
        float4 r1 = make_float4(0.f, 0.f, 0.f, 0.f);
#pragma unroll
        for (int d = 0; d < DD; d++) {
            int e = eixs[n * DD + d];
            float4 v0 = *(const float4*)(g_redge2 + (size_t)e * OUTD + 4 * cg);
            float4 v1 = *(const float4*)(g_redge2 + (size_t)e * OUTD + 64 + 4 * cg);
            r0.x += v0.x; r0.y += v0.y; r0.z += v0.z; r0.w += v0.w;
            r1.x += v1.x; r1.y += v1.y; r1.z += v1.z; r1.w += v1.w;
        }
        float o[8];
        upk2(acc[r][0], o[0], o[1]); upk2(acc[r][1], o[2], o[3]);
        upk2(acc[r][2], o[4], o[5]); upk2(acc[r][3], o[6], o[7]);
        const float* rr0 = (const float*)&r0;
        const float* rr1 = (const float*)&r1;
        float4 w0, w1v;
        w0.x = fmaxf((o[0] + degf * bb0[0] + rr0[0]) * invdeg, 0.f);
        w0.y = fmaxf((o[1] + degf * bb0[1] + rr0[1]) * invdeg, 0.f);
        w0.z = fmaxf((o[2] + degf * bb0[2] + rr0[2]) * invdeg, 0.f);
        w0.w = fmaxf((o[3] + degf * bb0[3] + rr0[3]) * invdeg, 0.f);
        w1v.x = fmaxf((o[4] + degf * bb1[0] + rr1[0]) * invdeg, 0.f);
        w1v.y = fmaxf((o[5] + degf * bb1[1] + rr1[1]) * invdeg, 0.f);
        w1v.z = fmaxf((o[6] + degf * bb1[2] + rr1[2]) * invdeg, 0.f);
        w1v.w = fmaxf((o[7] + degf * bb1[3] + rr1[3]) * invdeg, 0.f);
        *(float4*)(out + (size_t)(nb + n) * OUTD + 4 * cg)      = w0;
        *(float4*)(out + (size_t)(nb + n) * OUTD + 64 + 4 * cg) = w1v;
    }
}

// =====================================================================
extern "C" void kernel_launch(void* const* d_in, const int* in_sizes, int n_in,
                              void* d_out, int out_size)
{
    const float* X  = (const float*)d_in[0];
    const float* Wp = (const float*)d_in[1];
    const float* bp = (const float*)d_in[2];
    const float* Wq = (const float*)d_in[3];
    const float* bq = (const float*)d_in[4];
    const float* W1 = (const float*)d_in[5];
    const float* b1 = (const float*)d_in[6];
    const float* W2 = (const float*)d_in[7];
    const float* b2 = (const float*)d_in[8];
    const int*   en = (const int*)d_in[9];

    const int N  = in_sizes[0] / FEAT;
    const int EK = in_sizes[9];
    const int E  = EK / KK;
    const int deg = EK / N;
    const float num = powf((float)deg, 1.0f / (float)KK);
    const float C   = num * (1.0f / 6.0f);
    const int perm_edges = N / KK;

    cudaFuncSetAttribute(node_mlp_kernel,
                         cudaFuncAttributeMaxDynamicSharedMemorySize, SMEM1);

    node_mlp_kernel<<<N / 32, 256, SMEM1>>>(X, Wp, bp, W1, b1, W2, b2, num);
    edge_kernel<<<E / 8, 256>>>(en, C, perm_edges);
    out_kernel<<<N / 32, 256>>>(Wq, bq, (float*)d_out, (float)deg, 1.0f / (float)deg);
}

// round 13
// speedup vs baseline: 1.5713x; 1.0069x over previous
#include <cuda_runtime.h>
#include <cuda_bf16.h>
#include <mma.h>
#include <math.h>

using namespace nvcuda;

#define NN   100000
#define EE   200000
#define KK   4
#define DD   8
#define FEAT 256
#define RANK 64
#define HID  512
#define OUTD 128
#define NPC  64                    // nodes per CTA in MLP kernels
#define CTAS_MLP ((NN + NPC - 1) / NPC)   // 1563

typedef unsigned long long u64;
typedef unsigned int u32;
typedef unsigned short u16;

// ---------------- scratch (static device arrays; no allocation) ----------------
__device__ float g_scaled[(size_t)NN * RANK];
__device__ float g_emb2[(size_t)NN * OUTD];
__device__ float g_term[(size_t)NN * DD * RANK];
__device__ int   g_eidx[(size_t)NN * DD];
__device__ float g_redge2[(size_t)EE * OUTD];

// bf16 hi/lo split tensors (row-major, same layouts as sources)
__device__ __align__(16) u16 g_Xh[(size_t)NN * FEAT], g_Xl[(size_t)NN * FEAT];
__device__ __align__(16) u16 g_Wph[FEAT * RANK], g_Wpl[FEAT * RANK];
__device__ __align__(16) u16 g_W1h[FEAT * HID],  g_W1l[FEAT * HID];
__device__ __align__(16) u16 g_W2h[HID * OUTD],  g_W2l[HID * OUTD];
__device__ __align__(16) u16 g_Hh[(size_t)NN * HID], g_Hl[(size_t)NN * HID];

// ---------------- packed f32x2 helpers (edge/out kernels) ----------------
__device__ __forceinline__ u64 bcast2(float a) {
    u64 r; asm("mov.b64 %0, {%1, %1};" : "=l"(r) : "f"(a)); return r;
}
__device__ __forceinline__ void upk2(u64 p, float& a, float& b) {
    asm("mov.b64 {%0, %1}, %2;" : "=f"(a), "=f"(b) : "l"(p));
}
__device__ __forceinline__ u64 f2fma(u64 a, u64 b, u64 c) {
    u64 d; asm("fma.rn.f32x2 %0, %1, %2, %3;" : "=l"(d) : "l"(a), "l"(b), "l"(c)); return d;
}

// ---------------- bf16 pack/split ----------------
__device__ __forceinline__ u32 pk2(float lo, float hi) {
    // bits[15:0] = bf16(lo), bits[31:16] = bf16(hi)
    u32 u; asm("cvt.rn.bf16x2.f32 %0, %1, %2;" : "=r"(u) : "f"(hi), "f"(lo)); return u;
}
__device__ __forceinline__ float lof(u32 u) { return __uint_as_float(u << 16); }
__device__ __forceinline__ float hif(u32 u) { return __uint_as_float(u & 0xffff0000u); }

// ---------------- cp.async ----------------
__device__ __forceinline__ unsigned sm_u32(const void* p) {
    return (unsigned)__cvta_generic_to_shared(p);
}
__device__ __forceinline__ void cpa16(unsigned dst, const void* src) {
    asm volatile("cp.async.ca.shared.global [%0], [%1], 16;" :: "r"(dst), "l"(src));
}
__device__ __forceinline__ void cpa_commit() { asm volatile("cp.async.commit_group;"); }
__device__ __forceinline__ void cpa_wait0()  { asm volatile("cp.async.wait_group 0;"); }
__device__ __forceinline__ void cpa_wait1()  { asm volatile("cp.async.wait_group 1;"); }

// ---------------- WMMA types ----------------
typedef wmma::fragment<wmma::matrix_a, 16, 16, 16, __nv_bfloat16, wmma::row_major> frag_a;
typedef wmma::fragment<wmma::matrix_b, 16, 16, 16, __nv_bfloat16, wmma::row_major> frag_b;
typedef wmma::fragment<wmma::accumulator, 16, 16, 16, float> frag_c;

// =====================================================================
// prep_x: X f32 -> bf16 hi/lo (row-major [N][256])
// =====================================================================
__global__ __launch_bounds__(256) void prep_x_kernel(const float* __restrict__ X)
{
    int idx = blockIdx.x * 256 + threadIdx.x;        // < NN*FEAT/4 = 6,400,000
    float4 v = ((const float4*)X)[idx];
    u32 hp0 = pk2(v.x, v.y);
    u32 lp0 = pk2(v.x - lof(hp0), v.y - hif(hp0));
    u32 hp1 = pk2(v.z, v.w);
    u32 lp1 = pk2(v.z - lof(hp1), v.w - hif(hp1));
    ((uint2*)g_Xh)[idx] = make_uint2(hp0, hp1);
    ((uint2*)g_Xl)[idx] = make_uint2(lp0, lp1);
}

// =====================================================================
// prep_w: weights f32 -> bf16 hi/lo (layouts preserved)
// =====================================================================
__global__ __launch_bounds__(256) void prep_w_kernel(
    const float* __restrict__ Wp, const float* __restrict__ W1,
    const float* __restrict__ W2)
{
    int idx = blockIdx.x * 256 + threadIdx.x;        // < 131072
    {
        float v = W1[idx];
        u32 u = pk2(v, 0.f);
        u32 u2 = pk2(v - lof(u), 0.f);
        g_W1h[idx] = (u16)(u & 0xffffu);
        g_W1l[idx] = (u16)(u2 & 0xffffu);
    }
    if (idx < FEAT * RANK) {
        float v = Wp[idx];
        u32 u = pk2(v, 0.f);
        u32 u2 = pk2(v - lof(u), 0.f);
        g_Wph[idx] = (u16)(u & 0xffffu);
        g_Wpl[idx] = (u16)(u2 & 0xffffu);
    }
    if (idx < HID * OUTD) {
        float v = W2[idx];
        u32 u = pk2(v, 0.f);
        u32 u2 = pk2(v - lof(u), 0.f);
        g_W2h[idx] = (u16)(u & 0xffffu);
        g_W2l[idx] = (u16)(u2 & 0xffffu);
    }
}

// =====================================================================
// mlpA: 64 nodes/CTA, 256 threads, WMMA split-bf16.
//   Phase 1: emb1 = num*(X@Wp + bp) -> g_scaled
//   Phase 2: H = relu(X@W1 + b1) -> g_Hh/g_Hl (bf16 hi/lo, row-major)
// smem: Xh [64][264] | Xl [64][264] | B 4x[64][136] (db x hi/lo) | biases
// =====================================================================
#define XSTR 264
#define BSTR 136
#define A_XH 0
#define A_XL (NPC * XSTR * 2)                 // 33792
#define A_B  (2 * NPC * XSTR * 2)             // 67584
#define A_BSZ (NPC * BSTR * 2)                // 17408 per buffer
#define A_BIAS (A_B + 4 * A_BSZ)              // 137216
#define SMEM_A (A_BIAS + 64 * 4 + 512 * 4)    // +2304 -> 139520

__global__ __launch_bounds__(256) void mlpA_kernel(
    const float* __restrict__ bp, const float* __restrict__ b1, float num)
{
    extern __shared__ char smc[];
    __nv_bfloat16* Xh = (__nv_bfloat16*)(smc + A_XH);
    __nv_bfloat16* Xl = (__nv_bfloat16*)(smc + A_XL);
    float* bps = (float*)(smc + A_BIAS);
    float* b1s = (float*)(smc + A_BIAS + 256);
    float* scratch = (float*)(smc + A_B);     // reused after compute phases
    const int t = threadIdx.x;
    const int nb = blockIdx.x * NPC;
    const int w = t >> 5;
    const int wm = w & 1;                     // 2 M groups (rows 32*wm..)
    const int wn = w >> 1;                    // 4 N groups

    if (t < 64) bps[t] = bp[t];
    for (int i = t; i < 512; i += 256) b1s[i] = b1[i];

    // ---- X tile load (bf16 hi/lo, padded rows); OOB rows zeroed ----
    const unsigned xh_s = sm_u32(Xh), xl_s = sm_u32(Xl);
#pragma unroll
    for (int it = 0; it < 8; it++) {
        int task = t + it * 256;              // 64 rows x 32 16B-chunks
        int row = task >> 5, col8 = (task & 31) * 8;
        int node = nb + row;
        unsigned d = (unsigned)(row * XSTR + col8) * 2u;
        if (node < NN) {
            cpa16(xh_s + d, g_Xh + (size_t)node * FEAT + col8);
            cpa16(xl_s + d, g_Xl + (size_t)node * FEAT + col8);
        } else {
            *(uint4*)(smc + A_XH + d) = make_uint4(0, 0, 0, 0);
            *(uint4*)(smc + A_XL + d) = make_uint4(0, 0, 0, 0);
        }
    }

    // =================== Phase 1: X@Wp (N=64, K=256) ===================
    // stage Wp subchunk kc (64k x 64n) into buffer db
    auto stageP1 = [&](int kc, int db) {
        unsigned bh = sm_u32(smc + A_B + (db * 2 + 0) * A_BSZ);
        unsigned bl = sm_u32(smc + A_B + (db * 2 + 1) * A_BSZ);
#pragma unroll
        for (int it = 0; it < 2; it++) {
            int task = t + it * 256;          // 64 rows x 8 chunks
            int row = task >> 3, col8 = (task & 7) * 8;
            unsigned d = (unsigned)(row * BSTR + col8) * 2u;
            size_t s = (size_t)(kc * 64 + row) * RANK + col8;
            cpa16(bh + d, g_Wph + s);
            cpa16(bl + d, g_Wpl + s);
        }
    };

    frag_c acc1[2];
    wmma::fill_fragment(acc1[0], 0.f);
    wmma::fill_fragment(acc1[1], 0.f);

    stageP1(0, 0);
    cpa_commit();
    for (int kc = 0; kc < 4; kc++) {
        if (kc < 3) { stageP1(kc + 1, (kc + 1) & 1); cpa_commit(); }
        if (kc < 3) cpa_wait1(); else cpa_wait0();
        __syncthreads();
        const int db = kc & 1;
        const __nv_bfloat16* Bh = (const __nv_bfloat16*)(smc + A_B + (db * 2 + 0) * A_BSZ);
        const __nv_bfloat16* Bl = (const __nv_bfloat16*)(smc + A_B + (db * 2 + 1) * A_BSZ);
#pragma unroll
        for (int kt = 0; kt < 4; kt++) {
            frag_b bh, bl;
            wmma::load_matrix_sync(bh, Bh + kt * 16 * BSTR + wn * 16, BSTR);
            wmma::load_matrix_sync(bl, Bl + kt * 16 * BSTR + wn * 16, BSTR);
#pragma unroll
            for (int m = 0; m < 2; m++) {
                frag_a ah, al;
                const int r0 = (wm * 2 + m) * 16;
                const int k0 = kc * 64 + kt * 16;
                wmma::load_matrix_sync(ah, Xh + r0 * XSTR + k0, XSTR);
                wmma::load_matrix_sync(al, Xl + r0 * XSTR + k0, XSTR);
                wmma::mma_sync(acc1[m], ah, bh, acc1[m]);
                wmma::mma_sync(acc1[m], ah, bl, acc1[m]);
                wmma::mma_sync(acc1[m], al, bh, acc1[m]);
            }
        }
        __syncthreads();
    }
    // epilogue phase 1 -> g_scaled
#pragma unroll
    for (int m = 0; m < 2; m++)
        wmma::store_matrix_sync(scratch + ((wm * 2 + m) * 16) * 72 + wn * 16,
                                acc1[m], 72, wmma::mem_row_major);
    __syncthreads();
    {
        int row = t >> 2, c0 = (t & 3) * 16;
        int node = nb + row;
        if (node < NN) {
            float o[16];
#pragma unroll
            for (int j = 0; j < 16; j++)
                o[j] = num * (scratch[row * 72 + c0 + j] + bps[c0 + j]);
#pragma unroll
            for (int q = 0; q < 4; q++)
                *(float4*)(g_scaled + (size_t)node * RANK + c0 + q * 4) =
                    make_float4(o[q * 4], o[q * 4 + 1], o[q * 4 + 2], o[q * 4 + 3]);
        }
    }
    __syncthreads();

    // =================== Phase 2: X@W1 (N=512 in 4 chunks of 128) ===================
    for (int cn = 0; cn < 4; cn++) {
        auto stageP2 = [&](int kc, int db) {
            unsigned bh = sm_u32(smc + A_B + (db * 2 + 0) * A_BSZ);
            unsigned bl = sm_u32(smc + A_B + (db * 2 + 1) * A_BSZ);
#pragma unroll
            for (int it = 0; it < 4; it++) {
                int task = t + it * 256;      // 64 rows x 16 chunks
                int row = task >> 4, col8 = (task & 15) * 8;
                unsigned d = (unsigned)(row * BSTR + col8) * 2u;
                size_t s = (size_t)(kc * 64 + row) * HID + cn * 128 + col8;
                cpa16(bh + d, g_W1h + s);
                cpa16(bl + d, g_W1l + s);
            }
        };

        frag_c acc[2][2];
#pragma unroll
        for (int m = 0; m < 2; m++)
#pragma unroll
            for (int n = 0; n < 2; n++) wmma::fill_fragment(acc[m][n], 0.f);

        stageP2(0, 0);
        cpa_commit();
        for (int kc = 0; kc < 4; kc++) {
            if (kc < 3) { stageP2(kc + 1, (kc + 1) & 1); cpa_commit(); }
            if (kc < 3) cpa_wait1(); else cpa_wait0();
            __syncthreads();
            const int db = kc & 1;
            const __nv_bfloat16* Bh = (const __nv_bfloat16*)(smc + A_B + (db * 2 + 0) * A_BSZ);
            const __nv_bfloat16* Bl = (const __nv_bfloat16*)(smc + A_B + (db * 2 + 1) * A_BSZ);
#pragma unroll
            for (int kt = 0; kt < 4; kt++) {
                const int k0 = kc * 64 + kt * 16;
                frag_a ah[2], al[2];
#pragma unroll
                for (int m = 0; m < 2; m++) {
                    const int r0 = (wm * 2 + m) * 16;
                    wmma::load_matrix_sync(ah[m], Xh + r0 * XSTR + k0, XSTR);
                    wmma::load_matrix_sync(al[m], Xl + r0 * XSTR + k0, XSTR);
                }
                frag_b bh[2], bl[2];
#pragma unroll
                for (int n = 0; n < 2; n++) {
                    const int c0 = (wn * 2 + n) * 16;
                    wmma::load_matrix_sync(bh[n], Bh + kt * 16 * BSTR + c0, BSTR);
                    wmma::load_matrix_sync(bl[n], Bl + kt * 16 * BSTR + c0, BSTR);
                }
#pragma unroll
                for (int m = 0; m < 2; m++)
#pragma unroll
                    for (int n = 0; n < 2; n++) {
                        wmma::mma_sync(acc[m][n], ah[m], bh[n], acc[m][n]);
                        wmma::mma_sync(acc[m][n], ah[m], bl[n], acc[m][n]);
                        wmma::mma_sync(acc[m][n], al[m], bh[n], acc[m][n]);
                    }
            }
            __syncthreads();
        }
        // epilogue: bias+relu+split -> g_Hh/g_Hl
#pragma unroll
        for (int m = 0; m < 2; m++)
#pragma unroll
            for (int n = 0; n < 2; n++)
                wmma::store_matrix_sync(scratch + ((wm * 2 + m) * 16) * BSTR + (wn * 2 + n) * 16,
                                        acc[m][n], BSTR, wmma::mem_row_major);
        __syncthreads();
        {
            int row = t >> 2, c0 = (t & 3) * 32;
            int node = nb + row;
            if (node < NN) {
                u32 hps[16], lps[16];
#pragma unroll
                for (int j = 0; j < 16; j++) {
                    int c = c0 + j * 2;
                    float v0 = fmaxf(scratch[row * BSTR + c]     + b1s[cn * 128 + c],     0.f);
                    float v1 = fmaxf(scratch[row * BSTR + c + 1] + b1s[cn * 128 + c + 1], 0.f);
                    u32 ph = pk2(v0, v1);
                    lps[j] = pk2(v0 - lof(ph), v1 - hif(ph));
                    hps[j] = ph;
                }
                u16* dh = g_Hh + (size_t)node * HID + cn * 128 + c0;
                u16* dl = g_Hl + (size_t)node * HID + cn * 128 + c0;
#pragma unroll
                for (int q = 0; q < 4; q++) {
                    *(uint4*)(dh + q * 8) = make_uint4(hps[q * 4], hps[q * 4 + 1],
                                                       hps[q * 4 + 2], hps[q * 4 + 3]);
                    *(uint4*)(dl + q * 8) = make_uint4(lps[q * 4], lps[q * 4 + 1],
                                                       lps[q * 4 + 2], lps[q * 4 + 3]);
                }
            }
        }
        __syncthreads();
    }
}

// =====================================================================
// mlpB: emb2 = H@W2 + b2 -> g_emb2. 64 nodes/CTA, K=512, N=128.
// smem: Ah [64][520] | Al [64][520] | B 4x[64][136] | b2
// =====================================================================
#define HSTR 520
#define B_AH 0
#define B_AL (NPC * HSTR * 2)                 // 66560
#define B_B  (2 * NPC * HSTR * 2)             // 133120
#define B_BIAS (B_B + 4 * A_BSZ)              // 202752
#define SMEM_B (B_BIAS + 128 * 4)             // 203264

__global__ __launch_bounds__(256) void mlpB_kernel(const float* __restrict__ b2)
{
    extern __shared__ char smc[];
    __nv_bfloat16* Ah = (__nv_bfloat16*)(smc + B_AH);
    __nv_bfloat16* Al = (__nv_bfloat16*)(smc + B_AL);
    float* b2s = (float*)(smc + B_BIAS);
    float* scratch = (float*)(smc + B_B);
    const int t = threadIdx.x;
    const int nb = blockIdx.x * NPC;
    const int w = t >> 5;
    const int wm = w & 1;
    const int wn = w >> 1;

    if (t < 128) b2s[t] = b2[t];

    // A tile (H hi/lo)
    const unsigned ah_s = sm_u32(Ah), al_s = sm_u32(Al);
#pragma unroll
    for (int it = 0; it < 16; it++) {
        int task = t + it * 256;              // 64 rows x 64 chunks
        int row = task >> 6, col8 = (task & 63) * 8;
        int node = nb + row;
        unsigned d = (unsigned)(row * HSTR + col8) * 2u;
        if (node < NN) {
            cpa16(ah_s + d, g_Hh + (size_t)node * HID + col8);
            cpa16(al_s + d, g_Hl + (size_t)node * HID + col8);
        } else {
            *(uint4*)(smc + B_AH + d) = make_uint4(0, 0, 0, 0);
            *(uint4*)(smc + B_AL + d) = make_uint4(0, 0, 0, 0);
        }
    }

    auto stageB = [&](int kc, int db) {
        unsigned bh = sm_u32(smc + B_B + (db * 2 + 0) * A_BSZ);
        unsigned bl = sm_u32(smc + B_B + (db * 2 + 1) * A_BSZ);
#pragma unroll
        for (int it = 0; it < 4; it++) {
            int task = t + it * 256;
            int row = task >> 4, col8 = (task & 15) * 8;
            unsigned d = (unsigned)(row * BSTR + col8) * 2u;
            size_t s = (size_t)(kc * 64 + row) * OUTD + col8;
            cpa16(bh + d, g_W2h + s);
            cpa16(bl + d, g_W2l + s);
        }
    };

    frag_c acc[2][2];
#pragma unroll
    for (int m = 0; m < 2; m++)
#pragma unroll
        for (int n = 0; n < 2; n++) wmma::fill_fragment(acc[m][n], 0.f);

    stageB(0, 0);
    cpa_commit();
    for (int kc = 0; kc < 8; kc++) {
        if (kc < 7) { stageB(kc + 1, (kc + 1) & 1); cpa_commit(); }
        if (kc < 7) cpa_wait1(); else cpa_wait0();
        __syncthreads();
        const int db = kc & 1;
        const __nv_bfloat16* Bh = (const __nv_bfloat16*)(smc + B_B + (db * 2 + 0) * A_BSZ);
        const __nv_bfloat16* Bl = (const __nv_bfloat16*)(smc + B_B + (db * 2 + 1) * A_BSZ);
#pragma unroll
        for (int kt = 0; kt < 4; kt++) {
            const int k0 = kc * 64 + kt * 16;
            frag_a ah[2], al[2];
#pragma unroll
            for (int m = 0; m < 2; m++) {
                const int r0 = (wm * 2 + m) * 16;
                wmma::load_matrix_sync(ah[m], Ah + r0 * HSTR + k0, HSTR);
                wmma::load_matrix_sync(al[m], Al + r0 * HSTR + k0, HSTR);
            }
            frag_b bh[2], bl[2];
#pragma unroll
            for (int n = 0; n < 2; n++) {
                const int c0 = (wn * 2 + n) * 16;
                wmma::load_matrix_sync(bh[n], Bh + kt * 16 * BSTR + c0, BSTR);
                wmma::load_matrix_sync(bl[n], Bl + kt * 16 * BSTR + c0, BSTR);
            }
#pragma unroll
            for (int m = 0; m < 2; m++)
#pragma unroll
                for (int n = 0; n < 2; n++) {
                    wmma::mma_sync(acc[m][n], ah[m], bh[n], acc[m][n]);
                    wmma::mma_sync(acc[m][n], ah[m], bl[n], acc[m][n]);
                    wmma::mma_sync(acc[m][n], al[m], bh[n], acc[m][n]);
                }
        }
        __syncthreads();
    }

#pragma unroll
    for (int m = 0; m < 2; m++)
#pragma unroll
        for (int n = 0; n < 2; n++)
            wmma::store_matrix_sync(scratch + ((wm * 2 + m) * 16) * BSTR + (wn * 2 + n) * 16,
                                    acc[m][n], BSTR, wmma::mem_row_major);
    __syncthreads();
    {
        int row = t >> 2, c0 = (t & 3) * 32;
        int node = nb + row;
        if (node < NN) {
#pragma unroll
            for (int q = 0; q < 8; q++) {
                float4 o;
                o.x = scratch[row * BSTR + c0 + q * 4 + 0] + b2s[c0 + q * 4 + 0];
                o.y = scratch[row * BSTR + c0 + q * 4 + 1] + b2s[c0 + q * 4 + 1];
                o.z = scratch[row * BSTR + c0 + q * 4 + 2] + b2s[c0 + q * 4 + 2];
                o.w = scratch[row * BSTR + c0 + q * 4 + 3] + b2s[c0 + q * 4 + 3];
                *(float4*)(g_emb2 + (size_t)node * OUTD + c0 + q * 4) = o;
            }
        }
    }
}

// =====================================================================
// edge kernel (unchanged from best-passing)
// =====================================================================
__global__ __launch_bounds__(256) void edge_kernel(
    const int* __restrict__ en, float C, int perm_edges)
{
    const int lane = threadIdx.x & 31;
    const int e    = blockIdx.x * 8 + (threadIdx.x >> 5);

    int myn = 0;
    if (lane < 4) myn = en[e * 4 + lane];
    const unsigned m = 0xffffffffu;
    int n0 = __shfl_sync(m, myn, 0);
    int n1 = __shfl_sync(m, myn, 1);
    int n2 = __shfl_sync(m, myn, 2);
    int n3 = __shfl_sync(m, myn, 3);

    float2 g0 = *(const float2*)(g_scaled + (size_t)n0 * RANK + lane * 2);
    float2 g1 = *(const float2*)(g_scaled + (size_t)n1 * RANK + lane * 2);
    float2 g2 = *(const float2*)(g_scaled + (size_t)n2 * RANK + lane * 2);
    float2 g3 = *(const float2*)(g_scaled + (size_t)n3 * RANK + lane * 2);

    float2 a, b;
    a.x = g0.x * g1.x; a.y = g0.y * g1.y;
    b.x = g2.x * g3.x; b.y = g2.y * g3.y;
    float2 t0, t1, t2, t3;
    t0.x = tanhf(C * (g1.x * b.x)); t0.y = tanhf(C * (g1.y * b.y));
    t1.x = tanhf(C * (g0.x * b.x)); t1.y = tanhf(C * (g0.y * b.y));
    t2.x = tanhf(C * (a.x * g3.x)); t2.y = tanhf(C * (a.y * g3.y));
    t3.x = tanhf(C * (a.x * g2.x)); t3.y = tanhf(C * (a.y * g2.y));

    const int d = e / perm_edges;
    *(float2*)(g_term + ((size_t)n0 * DD + d) * RANK + lane * 2) = t0;
    *(float2*)(g_term + ((size_t)n1 * DD + d) * RANK + lane * 2) = t1;
    *(float2*)(g_term + ((size_t)n2 * DD + d) * RANK + lane * 2) = t2;
    *(float2*)(g_term + ((size_t)n3 * DD + d) * RANK + lane * 2) = t3;
    if (lane < 4) g_eidx[(size_t)myn * DD + d] = e;

    float4 s = make_float4(0.f, 0.f, 0.f, 0.f);
    float4 v;
    v = *(const float4*)(g_emb2 + (size_t)n0 * OUTD + lane * 4);
    s.x += v.x; s.y += v.y; s.z += v.z; s.w += v.w;
    v = *(const float4*)(g_emb2 + (size_t)n1 * OUTD + lane * 4);
    s.x += v.x; s.y += v.y; s.z += v.z; s.w += v.w;
    v = *(const float4*)(g_emb2 + (size_t)n2 * OUTD + lane * 4);
    s.x += v.x; s.y += v.y; s.z += v.z; s.w += v.w;
    v = *(const float4*)(g_emb2 + (size_t)n3 * OUTD + lane * 4);
    s.x += v.x; s.y += v.y; s.z += v.z; s.w += v.w;
    s.x = fmaxf(s.x, 0.f); s.y = fmaxf(s.y, 0.f);
    s.z = fmaxf(s.z, 0.f); s.w = fmaxf(s.w, 0.f);
    *(float4*)(g_redge2 + (size_t)e * OUTD + lane * 4) = s;
}

// =====================================================================
// out kernel (unchanged from best-passing)
// =====================================================================
__global__ __launch_bounds__(256) void out_kernel(
    const float* __restrict__ Wq, const float* __restrict__ bq,
    float* __restrict__ out, float degf, float invdeg)
{
    __shared__ float tsums[32 * RANK];
    __shared__ float Wqs[RANK * OUTD];
    __shared__ int   eixs[32 * DD];
    const int t  = threadIdx.x;
    const int nb = blockIdx.x * 32;

    {
        const float4* ws = (const float4*)Wq;
        float4* wd = (float4*)Wqs;
#pragma unroll
        for (int i = 0; i < 8; i++) wd[t + i * 256] = ws[t + i * 256];
    }
    eixs[t] = g_eidx[(size_t)nb * DD + t];

    {
        const int n = t >> 3;
        const int p = (t & 7) * 8;
        const float* src = g_term + (size_t)(nb + n) * DD * RANK + p;
        float4 s0 = make_float4(0.f, 0.f, 0.f, 0.f);
        float4 s1 = make_float4(0.f, 0.f, 0.f, 0.f);
#pragma unroll
        for (int d = 0; d < DD; d++) {
            float4 v0 = *(const float4*)(src + d * RANK);
            float4 v1 = *(const float4*)(src + d * RANK + 4);
            s0.x += v0.x; s0.y += v0.y; s0.z += v0.z; s0.w += v0.w;
            s1.x += v1.x; s1.y += v1.y; s1.z += v1.z; s1.w += v1.w;
        }
        *(float4*)(tsums + n * RANK + p)     = s0;
        *(float4*)(tsums + n * RANK + p + 4) = s1;
    }
    __syncthreads();

    const int n0 = (t >> 4) * 2;
    const int cg = t & 15;
    u64 acc[2][4];
#pragma unroll
    for (int r = 0; r < 2; r++)
#pragma unroll
        for (int j = 0; j < 4; j++) acc[r][j] = 0;

#pragma unroll
    for (int k4 = 0; k4 < RANK / 4; k4++) {
        float4 a40 = *(const float4*)(tsums + n0 * RANK + k4 * 4);
        float4 a41 = *(const float4*)(tsums + (n0 + 1) * RANK + k4 * 4);
#pragma unroll
        for (int kk = 0; kk < 4; kk++) {
            int k = k4 * 4 + kk;
            ulonglong2 b0 = *(const ulonglong2*)(Wqs + k * OUTD + 4 * cg);
            ulonglong2 b1v = *(const ulonglong2*)(Wqs + k * OUTD + 64 + 4 * cg);
            u64 av0 = bcast2(((const float*)&a40)[kk]);
            u64 av1 = bcast2(((const float*)&a41)[kk]);
            acc[0][0] = f2fma(av0, b0.x,  acc[0][0]);
            acc[0][1] = f2fma(av0, b0.y,  acc[0][1]);
            acc[0][2] = f2fma(av0, b1v.x, acc[0][2]);
            acc[0][3] = f2fma(av0, b1v.y, acc[0][3]);
            acc[1][0] = f2fma(av1, b0.x,  acc[1][0]);
            acc[1][1] = f2fma(av1, b0.y,  acc[1][1]);
            acc[1][2] = f2fma(av1, b1v.x, acc[1][2]);
            acc[1][3] = f2fma(av1, b1v.y, acc[1][3]);
        }
    }

    float4 bv0 = *(const float4*)(bq + 4 * cg);
    float4 bv1 = *(const float4*)(bq + 64 + 4 * cg);
    const float* bb0 = (const float*)&bv0;
    const float* bb1 = (const float*)&bv1;

#pragma unroll
    for (int r = 0; r < 2; r++) {
        const int n = n0 + r;
        float4 r0 = make_float4(0.f, 0.f, 0.f, 0.f);
        float4 r1 = make_float4(0.f, 0.f, 0.f, 0.f);
#pragma unroll
        for (int d = 0; d < DD; d++) {
            int e = eixs[n * DD + d];
            float4 v0 = *(const float4*)(g_redge2 + (size_t)e * OUTD + 4 * cg);
            float4 v1 = *(const float4*)(g_redge2 + (size_t)e * OUTD + 64 + 4 * cg);
            r0.x += v0.x; r0.y += v0.y; r0.z += v0.z; r0.w += v0.w;
            r1.x += v1.x; r1.y += v1.y; r1.z += v1.z; r1.w += v1.w;
        }
        float o[8];
        upk2(acc[r][0], o[0], o[1]); upk2(acc[r][1], o[2], o[3]);
        upk2(acc[r][2], o[4], o[5]); upk2(acc[r][3], o[6], o[7]);
        const float* rr0 = (const float*)&r0;
        const float* rr1 = (const float*)&r1;
        float4 w0, w1v;
        w0.x = fmaxf((o[0] + degf * bb0[0] + rr0[0]) * invdeg, 0.f);
        w0.y = fmaxf((o[1] + degf * bb0[1] + rr0[1]) * invdeg, 0.f);
        w0.z = fmaxf((o[2] + degf * bb0[2] + rr0[2]) * invdeg, 0.f);
        w0.w = fmaxf((o[3] + degf * bb0[3] + rr0[3]) * invdeg, 0.f);
        w1v.x = fmaxf((o[4] + degf * bb1[0] + rr1[0]) * invdeg, 0.f);
        w1v.y = fmaxf((o[5] + degf * bb1[1] + rr1[1]) * invdeg, 0.f);
        w1v.z = fmaxf((o[6] + degf * bb1[2] + rr1[2]) * invdeg, 0.f);
        w1v.w = fmaxf((o[7] + degf * bb1[3] + rr1[3]) * invdeg, 0.f);
        *(float4*)(out + (size_t)(nb + n) * OUTD + 4 * cg)      = w0;
        *(float4*)(out + (size_t)(nb + n) * OUTD + 64 + 4 * cg) = w1v;
    }
}

// =====================================================================
extern "C" void kernel_launch(void* const* d_in, const int* in_sizes, int n_in,
                              void* d_out, int out_size)
{
    const float* X  = (const float*)d_in[0];
    const float* Wp = (const float*)d_in[1];
    const float* bp = (const float*)d_in[2];
    const float* Wq = (const float*)d_in[3];
    const float* bq = (const float*)d_in[4];
    const float* W1 = (const float*)d_in[5];
    const float* b1 = (const float*)d_in[6];
    const float* W2 = (const float*)d_in[7];
    const float* b2 = (const float*)d_in[8];
    const int*   en = (const int*)d_in[9];

    const int N  = in_sizes[0] / FEAT;
    const int EK = in_sizes[9];
    const int E  = EK / KK;
    const int deg = EK / N;
    const float num = powf((float)deg, 1.0f / (float)KK);
    const float C   = num * (1.0f / 6.0f);
    const int perm_edges = N / KK;

    cudaFuncSetAttribute(mlpA_kernel, cudaFuncAttributeMaxDynamicSharedMemorySize, SMEM_A);
    cudaFuncSetAttribute(mlpB_kernel, cudaFuncAttributeMaxDynamicSharedMemorySize, SMEM_B);

    prep_x_kernel<<<(NN * FEAT / 4) / 256, 256>>>(X);
    prep_w_kernel<<<(FEAT * HID) / 256, 256>>>(Wp, W1, W2);
    mlpA_kernel<<<CTAS_MLP, 256, SMEM_A>>>(bp, b1, num);
    mlpB_kernel<<<CTAS_MLP, 256, SMEM_B>>>(b2);
    edge_kernel<<<E / 8, 256>>>(en, C, perm_edges);
    out_kernel<<<N / 32, 256>>>(Wq, bq, (float*)d_out, (float)deg, 1.0f / (float)deg);
}

// round 14
// speedup vs baseline: 2.3475x; 1.4940x over previous
#include <cuda_runtime.h>
#include <cuda_bf16.h>
#include <mma.h>
#include <math.h>

using namespace nvcuda;

#define NN   100000
#define EE   200000
#define KK   4
#define DD   8
#define FEAT 256
#define RANK 64
#define HID  512
#define OUTD 128
#define NPC  64
#define CTAS_MLP ((NN + NPC - 1) / NPC)   // 1563

typedef unsigned long long u64;
typedef unsigned int u32;
typedef unsigned short u16;

// ---------------- scratch (static device arrays; no allocation) ----------------
__device__ float g_scaled[(size_t)NN * RANK];
__device__ float g_emb2[(size_t)NN * OUTD];
__device__ float g_term[(size_t)NN * DD * RANK];
__device__ int   g_eidx[(size_t)NN * DD];
__device__ float g_redge2[(size_t)EE * OUTD];

__device__ __align__(16) u16 g_Xh[(size_t)NN * FEAT], g_Xl[(size_t)NN * FEAT];
__device__ __align__(16) u16 g_Wph[FEAT * RANK], g_Wpl[FEAT * RANK];
__device__ __align__(16) u16 g_W1h[FEAT * HID],  g_W1l[FEAT * HID];
__device__ __align__(16) u16 g_W2h[HID * OUTD],  g_W2l[HID * OUTD];
__device__ __align__(16) u16 g_Hh[(size_t)NN * HID], g_Hl[(size_t)NN * HID];

// ---------------- packed f32x2 helpers ----------------
__device__ __forceinline__ u64 bcast2(float a) {
    u64 r; asm("mov.b64 %0, {%1, %1};" : "=l"(r) : "f"(a)); return r;
}
__device__ __forceinline__ void upk2(u64 p, float& a, float& b) {
    asm("mov.b64 {%0, %1}, %2;" : "=f"(a), "=f"(b) : "l"(p));
}
__device__ __forceinline__ u64 f2fma(u64 a, u64 b, u64 c) {
    u64 d; asm("fma.rn.f32x2 %0, %1, %2, %3;" : "=l"(d) : "l"(a), "l"(b), "l"(c)); return d;
}

// ---------------- bf16 pack/split ----------------
__device__ __forceinline__ u32 pk2(float lo, float hi) {
    u32 u; asm("cvt.rn.bf16x2.f32 %0, %1, %2;" : "=r"(u) : "f"(hi), "f"(lo)); return u;
}
__device__ __forceinline__ float lof(u32 u) { return __uint_as_float(u << 16); }
__device__ __forceinline__ float hif(u32 u) { return __uint_as_float(u & 0xffff0000u); }

// ---------------- cp.async ----------------
__device__ __forceinline__ unsigned sm_u32(const void* p) {
    return (unsigned)__cvta_generic_to_shared(p);
}
__device__ __forceinline__ void cpa16(unsigned dst, const void* src) {
    asm volatile("cp.async.ca.shared.global [%0], [%1], 16;" :: "r"(dst), "l"(src));
}
__device__ __forceinline__ void cpa_commit() { asm volatile("cp.async.commit_group;"); }
__device__ __forceinline__ void cpa_wait0()  { asm volatile("cp.async.wait_group 0;"); }
__device__ __forceinline__ void cpa_wait1()  { asm volatile("cp.async.wait_group 1;"); }

// ---------------- WMMA types ----------------
typedef wmma::fragment<wmma::matrix_a, 16, 16, 16, __nv_bfloat16, wmma::row_major> frag_a;
typedef wmma::fragment<wmma::matrix_b, 16, 16, 16, __nv_bfloat16, wmma::row_major> frag_b;
typedef wmma::fragment<wmma::accumulator, 16, 16, 16, float> frag_c;

// =====================================================================
// prep kernels
// =====================================================================
__global__ __launch_bounds__(256) void prep_x_kernel(const float* __restrict__ X)
{
    int idx = blockIdx.x * 256 + threadIdx.x;
    float4 v = ((const float4*)X)[idx];
    u32 hp0 = pk2(v.x, v.y);
    u32 lp0 = pk2(v.x - lof(hp0), v.y - hif(hp0));
    u32 hp1 = pk2(v.z, v.w);
    u32 lp1 = pk2(v.z - lof(hp1), v.w - hif(hp1));
    ((uint2*)g_Xh)[idx] = make_uint2(hp0, hp1);
    ((uint2*)g_Xl)[idx] = make_uint2(lp0, lp1);
}

__global__ __launch_bounds__(256) void prep_w_kernel(
    const float* __restrict__ Wp, const float* __restrict__ W1,
    const float* __restrict__ W2)
{
    int idx = blockIdx.x * 256 + threadIdx.x;
    {
        float v = W1[idx];
        u32 u = pk2(v, 0.f);
        u32 u2 = pk2(v - lof(u), 0.f);
        g_W1h[idx] = (u16)(u & 0xffffu);
        g_W1l[idx] = (u16)(u2 & 0xffffu);
    }
    if (idx < FEAT * RANK) {
        float v = Wp[idx];
        u32 u = pk2(v, 0.f);
        u32 u2 = pk2(v - lof(u), 0.f);
        g_Wph[idx] = (u16)(u & 0xffffu);
        g_Wpl[idx] = (u16)(u2 & 0xffffu);
    }
    if (idx < HID * OUTD) {
        float v = W2[idx];
        u32 u = pk2(v, 0.f);
        u32 u2 = pk2(v - lof(u), 0.f);
        g_W2h[idx] = (u16)(u & 0xffffu);
        g_W2l[idx] = (u16)(u2 & 0xffffu);
    }
}

// =====================================================================
// mlpA: 64 nodes/CTA, 256 threads, 2 CTAs/SM.
//   Phase 1: emb1 -> g_scaled   (B chunks: 64k x 64n, stride 72)
//   Phase 2: H -> g_Hh/g_Hl     (B chunks: 32k x 128n, stride 136)
// smem: Xh|Xl [64][264] (67.6K) + B region 36.9K + biases -> ~104.7KB
// =====================================================================
#define XSTR 264
#define BSTR1 72
#define BSTR2 136
#define A_XH 0
#define A_XL (NPC * XSTR * 2)                 // 33792
#define A_B  (2 * NPC * XSTR * 2)             // 67584
#define A_B1SZ (64 * BSTR1 * 2)               // 9216
#define A_B2SZ (32 * BSTR2 * 2)               // 8704
#define A_BREG (4 * A_B1SZ)                   // 36864
#define A_BIAS (A_B + A_BREG)                 // 104448
#define SMEM_A (A_BIAS + 64 * 4 + 512 * 4)    // 106752

__global__ __launch_bounds__(256, 2) void mlpA_kernel(
    const float* __restrict__ bp, const float* __restrict__ b1, float num)
{
    extern __shared__ char smc[];
    __nv_bfloat16* Xh = (__nv_bfloat16*)(smc + A_XH);
    __nv_bfloat16* Xl = (__nv_bfloat16*)(smc + A_XL);
    float* bps = (float*)(smc + A_BIAS);
    float* b1s = (float*)(smc + A_BIAS + 256);
    float* scratch = (float*)(smc + A_B);
    const int t = threadIdx.x;
    const int nb = blockIdx.x * NPC;
    const int w = t >> 5;
    const int wm = w & 1;
    const int wn = w >> 1;

    if (t < 64) bps[t] = bp[t];
    for (int i = t; i < 512; i += 256) b1s[i] = b1[i];

    // X tile (resident, hi/lo)
    const unsigned xh_s = sm_u32(Xh), xl_s = sm_u32(Xl);
#pragma unroll
    for (int it = 0; it < 8; it++) {
        int task = t + it * 256;
        int row = task >> 5, col8 = (task & 31) * 8;
        int node = nb + row;
        unsigned d = (unsigned)(row * XSTR + col8) * 2u;
        if (node < NN) {
            cpa16(xh_s + d, g_Xh + (size_t)node * FEAT + col8);
            cpa16(xl_s + d, g_Xl + (size_t)node * FEAT + col8);
        } else {
            *(uint4*)(smc + A_XH + d) = make_uint4(0, 0, 0, 0);
            *(uint4*)(smc + A_XL + d) = make_uint4(0, 0, 0, 0);
        }
    }

    // ===== Phase 1: X@Wp, K=256 in 4 chunks of 64 =====
    auto stageP1 = [&](int kc, int db) {
        unsigned bh = sm_u32(smc + A_B + (db * 2 + 0) * A_B1SZ);
        unsigned bl = sm_u32(smc + A_B + (db * 2 + 1) * A_B1SZ);
#pragma unroll
        for (int it = 0; it < 2; it++) {
            int task = t + it * 256;          // 64 rows x 8 chunks
            int row = task >> 3, col8 = (task & 7) * 8;
            unsigned d = (unsigned)(row * BSTR1 + col8) * 2u;
            size_t s = (size_t)(kc * 64 + row) * RANK + col8;
            cpa16(bh + d, g_Wph + s);
            cpa16(bl + d, g_Wpl + s);
        }
    };

    frag_c acc1[2];
    wmma::fill_fragment(acc1[0], 0.f);
    wmma::fill_fragment(acc1[1], 0.f);

    stageP1(0, 0);
    cpa_commit();
    for (int kc = 0; kc < 4; kc++) {
        if (kc < 3) { stageP1(kc + 1, (kc + 1) & 1); cpa_commit(); }
        if (kc < 3) cpa_wait1(); else cpa_wait0();
        __syncthreads();
        const int db = kc & 1;
        const __nv_bfloat16* Bh = (const __nv_bfloat16*)(smc + A_B + (db * 2 + 0) * A_B1SZ);
        const __nv_bfloat16* Bl = (const __nv_bfloat16*)(smc + A_B + (db * 2 + 1) * A_B1SZ);
#pragma unroll
        for (int kt = 0; kt < 4; kt++) {
            frag_b bh, bl;
            wmma::load_matrix_sync(bh, Bh + kt * 16 * BSTR1 + wn * 16, BSTR1);
            wmma::load_matrix_sync(bl, Bl + kt * 16 * BSTR1 + wn * 16, BSTR1);
#pragma unroll
            for (int m = 0; m < 2; m++) {
                frag_a ah, al;
                const int r0 = (wm * 2 + m) * 16;
                const int k0 = kc * 64 + kt * 16;
                wmma::load_matrix_sync(ah, Xh + r0 * XSTR + k0, XSTR);
                wmma::load_matrix_sync(al, Xl + r0 * XSTR + k0, XSTR);
                wmma::mma_sync(acc1[m], ah, bh, acc1[m]);
                wmma::mma_sync(acc1[m], ah, bl, acc1[m]);
                wmma::mma_sync(acc1[m], al, bh, acc1[m]);
            }
        }
        __syncthreads();
    }
#pragma unroll
    for (int m = 0; m < 2; m++)
        wmma::store_matrix_sync(scratch + ((wm * 2 + m) * 16) * 72 + wn * 16,
                                acc1[m], 72, wmma::mem_row_major);
    __syncthreads();
    {
        int row = t >> 2, c0 = (t & 3) * 16;
        int node = nb + row;
        if (node < NN) {
            float o[16];
#pragma unroll
            for (int j = 0; j < 16; j++)
                o[j] = num * (scratch[row * 72 + c0 + j] + bps[c0 + j]);
#pragma unroll
            for (int q = 0; q < 4; q++)
                *(float4*)(g_scaled + (size_t)node * RANK + c0 + q * 4) =
                    make_float4(o[q * 4], o[q * 4 + 1], o[q * 4 + 2], o[q * 4 + 3]);
        }
    }
    __syncthreads();

    // ===== Phase 2: X@W1, 4 N-chunks of 128, K=256 in 8 chunks of 32 =====
    for (int cn = 0; cn < 4; cn++) {
        auto stageP2 = [&](int kc, int db) {
            unsigned bh = sm_u32(smc + A_B + (db * 2 + 0) * A_B2SZ);
            unsigned bl = sm_u32(smc + A_B + (db * 2 + 1) * A_B2SZ);
#pragma unroll
            for (int it = 0; it < 2; it++) {
                int task = t + it * 256;      // 32 rows x 16 chunks
                int row = task >> 4, col8 = (task & 15) * 8;
                unsigned d = (unsigned)(row * BSTR2 + col8) * 2u;
                size_t s = (size_t)(kc * 32 + row) * HID + cn * 128 + col8;
                cpa16(bh + d, g_W1h + s);
                cpa16(bl + d, g_W1l + s);
            }
        };

        frag_c acc[2][2];
#pragma unroll
        for (int m = 0; m < 2; m++)
#pragma unroll
            for (int n = 0; n < 2; n++) wmma::fill_fragment(acc[m][n], 0.f);

        stageP2(0, 0);
        cpa_commit();
        for (int kc = 0; kc < 8; kc++) {
            if (kc < 7) { stageP2(kc + 1, (kc + 1) & 1); cpa_commit(); }
            if (kc < 7) cpa_wait1(); else cpa_wait0();
            __syncthreads();
            const int db = kc & 1;
            const __nv_bfloat16* Bh = (const __nv_bfloat16*)(smc + A_B + (db * 2 + 0) * A_B2SZ);
            const __nv_bfloat16* Bl = (const __nv_bfloat16*)(smc + A_B + (db * 2 + 1) * A_B2SZ);
#pragma unroll
            for (int kt = 0; kt < 2; kt++) {
                const int k0 = kc * 32 + kt * 16;
                frag_a ah[2], al[2];
#pragma unroll
                for (int m = 0; m < 2; m++) {
                    const int r0 = (wm * 2 + m) * 16;
                    wmma::load_matrix_sync(ah[m], Xh + r0 * XSTR + k0, XSTR);
                    wmma::load_matrix_sync(al[m], Xl + r0 * XSTR + k0, XSTR);
                }
                frag_b bh[2], bl[2];
#pragma unroll
                for (int n = 0; n < 2; n++) {
                    const int c0 = (wn * 2 + n) * 16;
                    wmma::load_matrix_sync(bh[n], Bh + kt * 16 * BSTR2 + c0, BSTR2);
                    wmma::load_matrix_sync(bl[n], Bl + kt * 16 * BSTR2 + c0, BSTR2);
                }
#pragma unroll
                for (int m = 0; m < 2; m++)
#pragma unroll
                    for (int n = 0; n < 2; n++) {
                        wmma::mma_sync(acc[m][n], ah[m], bh[n], acc[m][n]);
                        wmma::mma_sync(acc[m][n], ah[m], bl[n], acc[m][n]);
                        wmma::mma_sync(acc[m][n], al[m], bh[n], acc[m][n]);
                    }
            }
            __syncthreads();
        }
#pragma unroll
        for (int m = 0; m < 2; m++)
#pragma unroll
            for (int n = 0; n < 2; n++)
                wmma::store_matrix_sync(scratch + ((wm * 2 + m) * 16) * BSTR2 + (wn * 2 + n) * 16,
                                        acc[m][n], BSTR2, wmma::mem_row_major);
        __syncthreads();
        {
            int row = t >> 2, c0 = (t & 3) * 32;
            int node = nb + row;
            if (node < NN) {
                u32 hps[16], lps[16];
#pragma unroll
                for (int j = 0; j < 16; j++) {
                    int c = c0 + j * 2;
                    float v0 = fmaxf(scratch[row * BSTR2 + c]     + b1s[cn * 128 + c],     0.f);
                    float v1 = fmaxf(scratch[row * BSTR2 + c + 1] + b1s[cn * 128 + c + 1], 0.f);
                    u32 ph = pk2(v0, v1);
                    lps[j] = pk2(v0 - lof(ph), v1 - hif(ph));
                    hps[j] = ph;
                }
                u16* dh = g_Hh + (size_t)node * HID + cn * 128 + c0;
                u16* dl = g_Hl + (size_t)node * HID + cn * 128 + c0;
#pragma unroll
                for (int q = 0; q < 4; q++) {
                    *(uint4*)(dh + q * 8) = make_uint4(hps[q * 4], hps[q * 4 + 1],
                                                       hps[q * 4 + 2], hps[q * 4 + 3]);
                    *(uint4*)(dl + q * 8) = make_uint4(lps[q * 4], lps[q * 4 + 1],
                                                       lps[q * 4 + 2], lps[q * 4 + 3]);
                }
            }
        }
        __syncthreads();
    }
}

// =====================================================================
// mlpB: emb2 = H@W2 + b2. 64 nodes/CTA, 2 CTAs/SM.
// A streamed in 64k chunks (stride 72), B 64k chunks (stride 136).
// smem: A 36.9K + B 69.6K + bias -> ~107KB
// =====================================================================
#define BA_STR 72
#define B_A   0
#define B_ASZ (64 * BA_STR * 2)               // 9216
#define B_B   (4 * B_ASZ)                     // 36864
#define B_BSZ (64 * BSTR2 * 2)                // 17408
#define B_BIAS (B_B + 4 * B_BSZ)              // 106496
#define SMEM_B (B_BIAS + 128 * 4)             // 107008

__global__ __launch_bounds__(256, 2) void mlpB_kernel(const float* __restrict__ b2)
{
    extern __shared__ char smc[];
    float* b2s = (float*)(smc + B_BIAS);
    float* scratch = (float*)(smc + B_B);
    const int t = threadIdx.x;
    const int nb = blockIdx.x * NPC;
    const int w = t >> 5;
    const int wm = w & 1;
    const int wn = w >> 1;

    if (t < 128) b2s[t] = b2[t];

    auto stageA = [&](int kc, int db) {
        unsigned ah = sm_u32(smc + B_A + (db * 2 + 0) * B_ASZ);
        unsigned al = sm_u32(smc + B_A + (db * 2 + 1) * B_ASZ);
#pragma unroll
        for (int it = 0; it < 2; it++) {
            int task = t + it * 256;          // 64 rows x 8 chunks
            int row = task >> 3, col8 = (task & 7) * 8;
            int node = nb + row;
            unsigned d = (unsigned)(row * BA_STR + col8) * 2u;
            if (node < NN) {
                size_t s = (size_t)node * HID + kc * 64 + col8;
                cpa16(ah + d, g_Hh + s);
                cpa16(al + d, g_Hl + s);
            } else {
                *(uint4*)(smc + B_A + (db * 2 + 0) * B_ASZ + d) = make_uint4(0, 0, 0, 0);
                *(uint4*)(smc + B_A + (db * 2 + 1) * B_ASZ + d) = make_uint4(0, 0, 0, 0);
            }
        }
    };
    auto stageB = [&](int kc, int db) {
        unsigned bh = sm_u32(smc + B_B + (db * 2 + 0) * B_BSZ);
        unsigned bl = sm_u32(smc + B_B + (db * 2 + 1) * B_BSZ);
#pragma unroll
        for (int it = 0; it < 4; it++) {
            int task = t + it * 256;          // 64 rows x 16 chunks
            int row = task >> 4, col8 = (task & 15) * 8;
            unsigned d = (unsigned)(row * BSTR2 + col8) * 2u;
            size_t s = (size_t)(kc * 64 + row) * OUTD + col8;
            cpa16(bh + d, g_W2h + s);
            cpa16(bl + d, g_W2l + s);
        }
    };

    frag_c acc[2][2];
#pragma unroll
    for (int m = 0; m < 2; m++)
#pragma unroll
        for (int n = 0; n < 2; n++) wmma::fill_fragment(acc[m][n], 0.f);

    stageA(0, 0);
    stageB(0, 0);
    cpa_commit();
    for (int kc = 0; kc < 8; kc++) {
        if (kc < 7) { stageA(kc + 1, (kc + 1) & 1); stageB(kc + 1, (kc + 1) & 1); cpa_commit(); }
        if (kc < 7) cpa_wait1(); else cpa_wait0();
        __syncthreads();
        const int db = kc & 1;
        const __nv_bfloat16* Ah = (const __nv_bfloat16*)(smc + B_A + (db * 2 + 0) * B_ASZ);
        const __nv_bfloat16* Al = (const __nv_bfloat16*)(smc + B_A + (db * 2 + 1) * B_ASZ);
        const __nv_bfloat16* Bh = (const __nv_bfloat16*)(smc + B_B + (db * 2 + 0) * B_BSZ);
        const __nv_bfloat16* Bl = (const __nv_bfloat16*)(smc + B_B + (db * 2 + 1) * B_BSZ);
#pragma unroll
        for (int kt = 0; kt < 4; kt++) {
            const int k0 = kt * 16;
            frag_a ah[2], al[2];
#pragma unroll
            for (int m = 0; m < 2; m++) {
                const int r0 = (wm * 2 + m) * 16;
                wmma::load_matrix_sync(ah[m], Ah + r0 * BA_STR + k0, BA_STR);
                wmma::load_matrix_sync(al[m], Al + r0 * BA_STR + k0, BA_STR);
            }
            frag_b bh[2], bl[2];
#pragma unroll
            for (int n = 0; n < 2; n++) {
                const int c0 = (wn * 2 + n) * 16;
                wmma::load_matrix_sync(bh[n], Bh + kt * 16 * BSTR2 + c0, BSTR2);
                wmma::load_matrix_sync(bl[n], Bl + kt * 16 * BSTR2 + c0, BSTR2);
            }
#pragma unroll
            for (int m = 0; m < 2; m++)
#pragma unroll
                for (int n = 0; n < 2; n++) {
                    wmma::mma_sync(acc[m][n], ah[m], bh[n], acc[m][n]);
                    wmma::mma_sync(acc[m][n], ah[m], bl[n], acc[m][n]);
                    wmma::mma_sync(acc[m][n], al[m], bh[n], acc[m][n]);
                }
        }
        __syncthreads();
    }

#pragma unroll
    for (int m = 0; m < 2; m++)
#pragma unroll
        for (int n = 0; n < 2; n++)
            wmma::store_matrix_sync(scratch + ((wm * 2 + m) * 16) * BSTR2 + (wn * 2 + n) * 16,
                                    acc[m][n], BSTR2, wmma::mem_row_major);
    __syncthreads();
    {
        int row = t >> 2, c0 = (t & 3) * 32;
        int node = nb + row;
        if (node < NN) {
#pragma unroll
            for (int q = 0; q < 8; q++) {
                float4 o;
                o.x = scratch[row * BSTR2 + c0 + q * 4 + 0] + b2s[c0 + q * 4 + 0];
                o.y = scratch[row * BSTR2 + c0 + q * 4 + 1] + b2s[c0 + q * 4 + 1];
                o.z = scratch[row * BSTR2 + c0 + q * 4 + 2] + b2s[c0 + q * 4 + 2];
                o.w = scratch[row * BSTR2 + c0 + q * 4 + 3] + b2s[c0 + q * 4 + 3];
                *(float4*)(g_emb2 + (size_t)node * OUTD + c0 + q * 4) = o;
            }
        }
    }
}

// =====================================================================
// edge kernel (unchanged)
// =====================================================================
__global__ __launch_bounds__(256) void edge_kernel(
    const int* __restrict__ en, float C, int perm_edges)
{
    const int lane = threadIdx.x & 31;
    const int e    = blockIdx.x * 8 + (threadIdx.x >> 5);

    int myn = 0;
    if (lane < 4) myn = en[e * 4 + lane];
    const unsigned m = 0xffffffffu;
    int n0 = __shfl_sync(m, myn, 0);
    int n1 = __shfl_sync(m, myn, 1);
    int n2 = __shfl_sync(m, myn, 2);
    int n3 = __shfl_sync(m, myn, 3);

    float2 g0 = *(const float2*)(g_scaled + (size_t)n0 * RANK + lane * 2);
    float2 g1 = *(const float2*)(g_scaled + (size_t)n1 * RANK + lane * 2);
    float2 g2 = *(const float2*)(g_scaled + (size_t)n2 * RANK + lane * 2);
    float2 g3 = *(const float2*)(g_scaled + (size_t)n3 * RANK + lane * 2);

    float2 a, b;
    a.x = g0.x * g1.x; a.y = g0.y * g1.y;
    b.x = g2.x * g3.x; b.y = g2.y * g3.y;
    float2 t0, t1, t2, t3;
    t0.x = tanhf(C * (g1.x * b.x)); t0.y = tanhf(C * (g1.y * b.y));
    t1.x = tanhf(C * (g0.x * b.x)); t1.y = tanhf(C * (g0.y * b.y));
    t2.x = tanhf(C * (a.x * g3.x)); t2.y = tanhf(C * (a.y * g3.y));
    t3.x = tanhf(C * (a.x * g2.x)); t3.y = tanhf(C * (a.y * g2.y));

    const int d = e / perm_edges;
    *(float2*)(g_term + ((size_t)n0 * DD + d) * RANK + lane * 2) = t0;
    *(float2*)(g_term + ((size_t)n1 * DD + d) * RANK + lane * 2) = t1;
    *(float2*)(g_term + ((size_t)n2 * DD + d) * RANK + lane * 2) = t2;
    *(float2*)(g_term + ((size_t)n3 * DD + d) * RANK + lane * 2) = t3;
    if (lane < 4) g_eidx[(size_t)myn * DD + d] = e;

    float4 s = make_float4(0.f, 0.f, 0.f, 0.f);
    float4 v;
    v = *(const float4*)(g_emb2 + (size_t)n0 * OUTD + lane * 4);
    s.x += v.x; s.y += v.y; s.z += v.z; s.w += v.w;
    v = *(const float4*)(g_emb2 + (size_t)n1 * OUTD + lane * 4);
    s.x += v.x; s.y += v.y; s.z += v.z; s.w += v.w;
    v = *(const float4*)(g_emb2 + (size_t)n2 * OUTD + lane * 4);
    s.x += v.x; s.y += v.y; s.z += v.z; s.w += v.w;
    v = *(const float4*)(g_emb2 + (size_t)n3 * OUTD + lane * 4);
    s.x += v.x; s.y += v.y; s.z += v.z; s.w += v.w;
    s.x = fmaxf(s.x, 0.f); s.y = fmaxf(s.y, 0.f);
    s.z = fmaxf(s.z, 0.f); s.w = fmaxf(s.w, 0.f);
    *(float4*)(g_redge2 + (size_t)e * OUTD + lane * 4) = s;
}

// =====================================================================
// out kernel (unchanged)
// =====================================================================
__global__ __launch_bounds__(256) void out_kernel(
    const float* __restrict__ Wq, const float* __restrict__ bq,
    float* __restrict__ out, float degf, float invdeg)
{
    __shared__ float tsums[32 * RANK];
    __shared__ float Wqs[RANK * OUTD];
    __shared__ int   eixs[32 * DD];
    const int t  = threadIdx.x;
    const int nb = blockIdx.x * 32;

    {
        const float4* ws = (const float4*)Wq;
        float4* wd = (float4*)Wqs;
#pragma unroll
        for (int i = 0; i < 8; i++) wd[t + i * 256] = ws[t + i * 256];
    }
    eixs[t] = g_eidx[(size_t)nb * DD + t];

    {
        const int n = t >> 3;
        const int p = (t & 7) * 8;
        const float* src = g_term + (size_t)(nb + n) * DD * RANK + p;
        float4 s0 = make_float4(0.f, 0.f, 0.f, 0.f);
        float4 s1 = make_float4(0.f, 0.f, 0.f, 0.f);
#pragma unroll
        for (int d = 0; d < DD; d++) {
            float4 v0 = *(const float4*)(src + d * RANK);
            float4 v1 = *(const float4*)(src + d * RANK + 4);
            s0.x += v0.x; s0.y += v0.y; s0.z += v0.z; s0.w += v0.w;
            s1.x += v1.x; s1.y += v1.y; s1.z += v1.z; s1.w += v1.w;
        }
        *(float4*)(tsums + n * RANK + p)     = s0;
        *(float4*)(tsums + n * RANK + p + 4) = s1;
    }
    __syncthreads();

    const int n0 = (t >> 4) * 2;
    const int cg = t & 15;
    u64 acc[2][4];
#pragma unroll
    for (int r = 0; r < 2; r++)
#pragma unroll
        for (int j = 0; j < 4; j++) acc[r][j] = 0;

#pragma unroll
    for (int k4 = 0; k4 < RANK / 4; k4++) {
        float4 a40 = *(const float4*)(tsums + n0 * RANK + k4 * 4);
        float4 a41 = *(const float4*)(tsums + (n0 + 1) * RANK + k4 * 4);
#pragma unroll
        for (int kk = 0; kk < 4; kk++) {
            int k = k4 * 4 + kk;
            ulonglong2 b0 = *(const ulonglong2*)(Wqs + k * OUTD + 4 * cg);
            ulonglong2 b1v = *(const ulonglong2*)(Wqs + k * OUTD + 64 + 4 * cg);
            u64 av0 = bcast2(((const float*)&a40)[kk]);
            u64 av1 = bcast2(((const float*)&a41)[kk]);
            acc[0][0] = f2fma(av0, b0.x,  acc[0][0]);
            acc[0][1] = f2fma(av0, b0.y,  acc[0][1]);
            acc[0][2] = f2fma(av0, b1v.x, acc[0][2]);
            acc[0][3] = f2fma(av0, b1v.y, acc[0][3]);
            acc[1][0] = f2fma(av1, b0.x,  acc[1][0]);
            acc[1][1] = f2fma(av1, b0.y,  acc[1][1]);
            acc[1][2] = f2fma(av1, b1v.x, acc[1][2]);
            acc[1][3] = f2fma(av1, b1v.y, acc[1][3]);
        }
    }

    float4 bv0 = *(const float4*)(bq + 4 * cg);
    float4 bv1 = *(const float4*)(bq + 64 + 4 * cg);
    const float* bb0 = (const float*)&bv0;
    const float* bb1 = (const float*)&bv1;

#pragma unroll
    for (int r = 0; r < 2; r++) {
        const int n = n0 + r;
        float4 r0 = make_float4(0.f, 0.f, 0.f, 0.f);
        float4 r1 = make_float4(0.f, 0.f, 0.f, 0.f);
#pragma unroll
        for (int d = 0; d < DD; d++) {
            int e = eixs[n * DD + d];
            float4 v0 = *(const float4*)(g_redge2 + (size_t)e * OUTD + 4 * cg);
            float4 v1 = *(const float4*)(g_redge2 + (size_t)e * OUTD + 64 + 4 * cg);
            r0.x += v0.x; r0.y += v0.y; r0.z += v0.z; r0.w += v0.w;
            r1.x += v1.x; r1.y += v1.y; r1.z += v1.z; r1.w += v1.w;
        }
        float o[8];
        upk2(acc[r][0], o[0], o[1]); upk2(acc[r][1], o[2], o[3]);
        upk2(acc[r][2], o[4], o[5]); upk2(acc[r][3], o[6], o[7]);
        const float* rr0 = (const float*)&r0;
        const float* rr1 = (const float*)&r1;
        float4 w0, w1v;
        w0.x = fmaxf((o[0] + degf * bb0[0] + rr0[0]) * invdeg, 0.f);
        w0.y = fmaxf((o[1] + degf * bb0[1] + rr0[1]) * invdeg, 0.f);
        w0.z = fmaxf((o[2] + degf * bb0[2] + rr0[2]) * invdeg, 0.f);
        w0.w = fmaxf((o[3] + degf * bb0[3] + rr0[3]) * invdeg, 0.f);
        w1v.x = fmaxf((o[4] + degf * bb1[0] + rr1[0]) * invdeg, 0.f);
        w1v.y = fmaxf((o[5] + degf * bb1[1] + rr1[1]) * invdeg, 0.f);
        w1v.z = fmaxf((o[6] + degf * bb1[2] + rr1[2]) * invdeg, 0.f);
        w1v.w = fmaxf((o[7] + degf * bb1[3] + rr1[3]) * invdeg, 0.f);
        *(float4*)(out + (size_t)(nb + n) * OUTD + 4 * cg)      = w0;
        *(float4*)(out + (size_t)(nb + n) * OUTD + 64 + 4 * cg) = w1v;
    }
}

// =====================================================================
extern "C" void kernel_launch(void* const* d_in, const int* in_sizes, int n_in,
                              void* d_out, int out_size)
{
    const float* X  = (const float*)d_in[0];
    const float* Wp = (const float*)d_in[1];
    const float* bp = (const float*)d_in[2];
    const float* Wq = (const float*)d_in[3];
    const float* bq = (const float*)d_in[4];
    const float* W1 = (const float*)d_in[5];
    const float* b1 = (const float*)d_in[6];
    const float* W2 = (const float*)d_in[7];
    const float* b2 = (const float*)d_in[8];
    const int*   en = (const int*)d_in[9];

    const int N  = in_sizes[0] / FEAT;
    const int EK = in_sizes[9];
    const int E  = EK / KK;
    const int deg = EK / N;
    const float num = powf((float)deg, 1.0f / (float)KK);
    const float C   = num * (1.0f / 6.0f);
    const int perm_edges = N / KK;

    cudaFuncSetAttribute(mlpA_kernel, cudaFuncAttributeMaxDynamicSharedMemorySize, SMEM_A);
    cudaFuncSetAttribute(mlpB_kernel, cudaFuncAttributeMaxDynamicSharedMemorySize, SMEM_B);

    prep_x_kernel<<<(NN * FEAT / 4) / 256, 256>>>(X);
    prep_w_kernel<<<(FEAT * HID) / 256, 256>>>(Wp, W1, W2);
    mlpA_kernel<<<CTAS_MLP, 256, SMEM_A>>>(bp, b1, num);
    mlpB_kernel<<<CTAS_MLP, 256, SMEM_B>>>(b2);
    edge_kernel<<<E / 8, 256>>>(en, C, perm_edges);
    out_kernel<<<N / 32, 256>>>(Wq, bq, (float*)d_out, (float)deg, 1.0f / (float)deg);
}

// round 16
// speedup vs baseline: 2.3978x; 1.0214x over previous
#include <cuda_runtime.h>
#include <cuda_bf16.h>
#include <mma.h>
#include <math.h>

using namespace nvcuda;

#define NN   100000
#define EE   200000
#define KK   4
#define DD   8
#define FEAT 256
#define RANK 64
#define HID  512
#define OUTD 128
#define NPC  64
#define CTAS_MLP ((NN + NPC - 1) / NPC)   // 1563

typedef unsigned long long u64;
typedef unsigned int u32;
typedef unsigned short u16;

// ---------------- scratch (static device arrays; no allocation) ----------------
__device__ float g_scaled[(size_t)NN * RANK];
__device__ float g_emb2[(size_t)NN * OUTD];
__device__ float g_term[(size_t)NN * DD * RANK];
__device__ int   g_eidx[(size_t)NN * DD];
__device__ float g_redge2[(size_t)EE * OUTD];

__device__ __align__(16) u16 g_Wph[FEAT * RANK], g_Wpl[FEAT * RANK];
__device__ __align__(16) u16 g_W1h[FEAT * HID],  g_W1l[FEAT * HID];
__device__ __align__(16) u16 g_W2h[HID * OUTD],  g_W2l[HID * OUTD];
__device__ __align__(16) u16 g_Hh[(size_t)NN * HID], g_Hl[(size_t)NN * HID];

// ---------------- packed f32x2 helpers ----------------
__device__ __forceinline__ u64 bcast2(float a) {
    u64 r; asm("mov.b64 %0, {%1, %1};" : "=l"(r) : "f"(a)); return r;
}
__device__ __forceinline__ void upk2(u64 p, float& a, float& b) {
    asm("mov.b64 {%0, %1}, %2;" : "=f"(a), "=f"(b) : "l"(p));
}
__device__ __forceinline__ u64 f2fma(u64 a, u64 b, u64 c) {
    u64 d; asm("fma.rn.f32x2 %0, %1, %2, %3;" : "=l"(d) : "l"(a), "l"(b), "l"(c)); return d;
}

// ---------------- bf16 pack/split ----------------
__device__ __forceinline__ u32 pk2(float lo, float hi) {
    u32 u; asm("cvt.rn.bf16x2.f32 %0, %1, %2;" : "=r"(u) : "f"(hi), "f"(lo)); return u;
}
__device__ __forceinline__ float lof(u32 u) { return __uint_as_float(u << 16); }
__device__ __forceinline__ float hif(u32 u) { return __uint_as_float(u & 0xffff0000u); }

// ---------------- cp.async ----------------
__device__ __forceinline__ unsigned sm_u32(const void* p) {
    return (unsigned)__cvta_generic_to_shared(p);
}
__device__ __forceinline__ void cpa16(unsigned dst, const void* src) {
    asm volatile("cp.async.ca.shared.global [%0], [%1], 16;" :: "r"(dst), "l"(src));
}
__device__ __forceinline__ void cpa_commit() { asm volatile("cp.async.commit_group;"); }
__device__ __forceinline__ void cpa_wait0()  { asm volatile("cp.async.wait_group 0;"); }
__device__ __forceinline__ void cpa_wait2()  { asm volatile("cp.async.wait_group 2;"); }

// ---------------- WMMA types ----------------
typedef wmma::fragment<wmma::matrix_a, 16, 16, 16, __nv_bfloat16, wmma::row_major> frag_a;
typedef wmma::fragment<wmma::matrix_b, 16, 16, 16, __nv_bfloat16, wmma::row_major> frag_b;
typedef wmma::fragment<wmma::accumulator, 16, 16, 16, float> frag_c;

// =====================================================================
// prep_w: weights f32 -> bf16 hi/lo (layouts preserved)
// =====================================================================
__global__ __launch_bounds__(256) void prep_w_kernel(
    const float* __restrict__ Wp, const float* __restrict__ W1,
    const float* __restrict__ W2)
{
    int idx = blockIdx.x * 256 + threadIdx.x;
    {
        float v = W1[idx];
        u32 u = pk2(v, 0.f);
        u32 u2 = pk2(v - lof(u), 0.f);
        g_W1h[idx] = (u16)(u & 0xffffu);
        g_W1l[idx] = (u16)(u2 & 0xffffu);
    }
    if (idx < FEAT * RANK) {
        float v = Wp[idx];
        u32 u = pk2(v, 0.f);
        u32 u2 = pk2(v - lof(u), 0.f);
        g_Wph[idx] = (u16)(u & 0xffffu);
        g_Wpl[idx] = (u16)(u2 & 0xffffu);
    }
    if (idx < HID * OUTD) {
        float v = W2[idx];
        u32 u = pk2(v, 0.f);
        u32 u2 = pk2(v - lof(u), 0.f);
        g_W2h[idx] = (u16)(u & 0xffffu);
        g_W2l[idx] = (u16)(u2 & 0xffffu);
    }
}

// =====================================================================
// mlpA: 64 nodes/CTA, 256 threads, 2 CTAs/SM. 4-deep cp.async pipeline.
//   Phase 0: load+split X f32 -> Xh/Xl smem (staged through B region)
//   Phase 1: emb1 -> g_scaled   (B chunks: 64k x 64n, stride 72)
//   Phase 2: H -> g_Hh/g_Hl     (B chunks: 32k x 128n, stride 136)
// =====================================================================
#define XSTR 264
#define BSTR1 72
#define BSTR2 136
#define A_XH 0
#define A_XL (NPC * XSTR * 2)                 // 33792
#define A_B  (2 * NPC * XSTR * 2)             // 67584
#define A_B1SZ (64 * BSTR1 * 2)               // 9216
#define A_B2SZ (32 * BSTR2 * 2)               // 8704
#define A_BREG (4 * A_B1SZ)                   // 36864
#define A_BIAS (A_B + A_BREG)                 // 104448
#define SMEM_A (A_BIAS + 64 * 4 + 512 * 4)    // 106752

__global__ __launch_bounds__(256, 2) void mlpA_kernel(
    const float* __restrict__ X,
    const float* __restrict__ bp, const float* __restrict__ b1, float num)
{
    extern __shared__ char smc[];
    __nv_bfloat16* Xh = (__nv_bfloat16*)(smc + A_XH);
    __nv_bfloat16* Xl = (__nv_bfloat16*)(smc + A_XL);
    float* bps = (float*)(smc + A_BIAS);
    float* b1s = (float*)(smc + A_BIAS + 256);
    float* scratch = (float*)(smc + A_B);
    const int t = threadIdx.x;
    const int nb = blockIdx.x * NPC;
    const int w = t >> 5;
    const int wm = w & 1;
    const int wn = w >> 1;

    if (t < 64) bps[t] = bp[t];
    for (int i = t; i < 512; i += 256) b1s[i] = b1[i];

    // ===== Phase 0: X f32 -> Xh/Xl (2 passes of 32 rows via staging) =====
    {
        const unsigned stg = sm_u32(smc + A_B);
        for (int p = 0; p < 2; p++) {
#pragma unroll
            for (int it = 0; it < 8; it++) {
                int task = t + it * 256;          // 32 rows x 64 float4
                int row = task >> 6, c4 = task & 63;
                int node = nb + p * 32 + row;
                if (node < NN)
                    cpa16(stg + (unsigned)task * 16u, X + (size_t)node * FEAT + c4 * 4);
                else
                    *(uint4*)(smc + A_B + task * 16) = make_uint4(0, 0, 0, 0);
            }
            cpa_commit(); cpa_wait0();
            __syncthreads();
#pragma unroll
            for (int it = 0; it < 8; it++) {
                int task = t + it * 256;
                int row = task >> 6, c4 = task & 63;
                float4 v = ((const float4*)(smc + A_B))[task];
                u32 hp0 = pk2(v.x, v.y), hp1 = pk2(v.z, v.w);
                u32 lp0 = pk2(v.x - lof(hp0), v.y - hif(hp0));
                u32 lp1 = pk2(v.z - lof(hp1), v.w - hif(hp1));
                unsigned off = (unsigned)((p * 32 + row) * XSTR + c4 * 4) * 2u;
                *(uint2*)(smc + A_XH + off) = make_uint2(hp0, hp1);
                *(uint2*)(smc + A_XL + off) = make_uint2(lp0, lp1);
            }
            __syncthreads();
        }
    }

    // ===== Phase 1: X@Wp, K=256 in 4 chunks of 64, 4-deep pipeline =====
    auto stageP1 = [&](int kc) {
        int db = kc & 3;
        unsigned bh = sm_u32(smc + A_B + db * A_B1SZ);
#pragma unroll
        for (int it = 0; it < 2; it++) {
            int task = t + it * 256;              // 64 rows x 8 chunks (hi then lo split by halves)
            int row = task >> 3, col8 = (task & 7) * 8;
            unsigned d = (unsigned)(row * BSTR1 + col8) * 2u;
            size_t s = (size_t)(kc * 64 + row) * RANK + col8;
            if (it == 0) cpa16(bh + d, g_Wph + s);
            else         cpa16(bh + d, g_Wpl + s);
        }
    };
    // NOTE: buffers hold hi in rows addressed by it=0 tasks and lo in it=1 tasks?
    // -> No: keep hi/lo in separate halves of a double-size buffer instead.
    // (see corrected staging below)

    // Corrected phase-1 staging: hi at buffer base, lo at +A_B1SZ/2 is wrong for
    // stride reasons; use paired buffers: buffer db covers hi, db^1 pattern breaks
    // the 4-deep scheme. Simplest correct: each buffer holds both hi(64x72) and
    // lo(64x72) packed sequentially -> A_B1SZ covers hi only, so allocate lo at
    // A_B + 4*A_B1SZ? exceeds region. Instead: stage hi+lo interleaved by rows:
    // rows 0..63 = hi, handled via two cpa16 per thread above with distinct d.
    // To keep this sound we place lo at d + 64*BSTR1*2 inside a 2x-sized buffer.
    // Buffers: 2 of size 2*A_B1SZ (double-buffer, not 4-deep) for phase 1 only.
    (void)0;

    frag_c acc1[2];
    wmma::fill_fragment(acc1[0], 0.f);
    wmma::fill_fragment(acc1[1], 0.f);

    {
        auto stage1 = [&](int kc, int db) {
            unsigned bh = sm_u32(smc + A_B + (db * 2 + 0) * A_B1SZ);
            unsigned bl = sm_u32(smc + A_B + (db * 2 + 1) * A_B1SZ);
#pragma unroll
            for (int it = 0; it < 2; it++) {
                int task = t + it * 256;
                int row = task >> 3, col8 = (task & 7) * 8;
                unsigned d = (unsigned)(row * BSTR1 + col8) * 2u;
                size_t s = (size_t)(kc * 64 + row) * RANK + col8;
                cpa16(bh + d, g_Wph + s);
                cpa16(bl + d, g_Wpl + s);
            }
        };
        stage1(0, 0);
        cpa_commit();
        for (int kc = 0; kc < 4; kc++) {
            if (kc < 3) stage1(kc + 1, (kc + 1) & 1);
            cpa_commit();                         // always commit (may be empty)
            asm volatile("cp.async.wait_group 1;");
            __syncthreads();
            const int db = kc & 1;
            const __nv_bfloat16* Bh = (const __nv_bfloat16*)(smc + A_B + (db * 2 + 0) * A_B1SZ);
            const __nv_bfloat16* Bl = (const __nv_bfloat16*)(smc + A_B + (db * 2 + 1) * A_B1SZ);
#pragma unroll
            for (int kt = 0; kt < 4; kt++) {
                frag_b bh, bl;
                wmma::load_matrix_sync(bh, Bh + kt * 16 * BSTR1 + wn * 16, BSTR1);
                wmma::load_matrix_sync(bl, Bl + kt * 16 * BSTR1 + wn * 16, BSTR1);
#pragma unroll
                for (int m = 0; m < 2; m++) {
                    frag_a ah, al;
                    const int r0 = (wm * 2 + m) * 16;
                    const int k0 = kc * 64 + kt * 16;
                    wmma::load_matrix_sync(ah, Xh + r0 * XSTR + k0, XSTR);
                    wmma::load_matrix_sync(al, Xl + r0 * XSTR + k0, XSTR);
                    wmma::mma_sync(acc1[m], ah, bh, acc1[m]);
                    wmma::mma_sync(acc1[m], ah, bl, acc1[m]);
                    wmma::mma_sync(acc1[m], al, bh, acc1[m]);
                }
            }
            __syncthreads();
        }
    }
#pragma unroll
    for (int m = 0; m < 2; m++)
        wmma::store_matrix_sync(scratch + ((wm * 2 + m) * 16) * 72 + wn * 16,
                                acc1[m], 72, wmma::mem_row_major);
    __syncthreads();
    {
        int row = t >> 2, c0 = (t & 3) * 16;
        int node = nb + row;
        if (node < NN) {
            float o[16];
#pragma unroll
            for (int j = 0; j < 16; j++)
                o[j] = num * (scratch[row * 72 + c0 + j] + bps[c0 + j]);
#pragma unroll
            for (int q = 0; q < 4; q++)
                *(float4*)(g_scaled + (size_t)node * RANK + c0 + q * 4) =
                    make_float4(o[q * 4], o[q * 4 + 1], o[q * 4 + 2], o[q * 4 + 3]);
        }
    }
    __syncthreads();

    // ===== Phase 2: X@W1, 4 N-chunks of 128, K in 8 chunks of 32, 4-deep =====
    for (int cn = 0; cn < 4; cn++) {
        auto stage2 = [&](int kc) {
            int db = kc & 3;
            unsigned bb = sm_u32(smc + A_B + db * (2 * A_B2SZ) / 2);  // see layout note
            (void)bb;
            unsigned bh = sm_u32(smc + A_B + db * A_B2SZ);
            // hi in first half rows? -> hi/lo stacked: hi at bh, lo at bh + 16*BSTR2*2
            // buffer db spans A_B2SZ bytes = 32 rows * BSTR2; we store hi rows 0..15? 
            // Layout: hi = rows [0,32) needs 32*BSTR2*2 = A_B2SZ, lo needs same.
            // So pair buffers: hi in db, lo in db+4? That needs 8*A_B2SZ=69.6KB > region.
            // Fall back to double-buffer (2 pairs) like before:
            (void)bh;
        };
        (void)stage2;

        auto stageP2 = [&](int kc, int db) {
            unsigned bh = sm_u32(smc + A_B + (db * 2 + 0) * A_B2SZ);
            unsigned bl = sm_u32(smc + A_B + (db * 2 + 1) * A_B2SZ);
#pragma unroll
            for (int it = 0; it < 2; it++) {
                int task = t + it * 256;
                int row = task >> 4, col8 = (task & 15) * 8;
                unsigned d = (unsigned)(row * BSTR2 + col8) * 2u;
                size_t s = (size_t)(kc * 32 + row) * HID + cn * 128 + col8;
                cpa16(bh + d, g_W1h + s);
                cpa16(bl + d, g_W1l + s);
            }
        };

        frag_c acc[2][2];
#pragma unroll
        for (int m = 0; m < 2; m++)
#pragma unroll
            for (int n = 0; n < 2; n++) wmma::fill_fragment(acc[m][n], 0.f);

        stageP2(0, 0);
        cpa_commit();
        for (int kc = 0; kc < 8; kc++) {
            if (kc < 7) stageP2(kc + 1, (kc + 1) & 1);
            cpa_commit();
            asm volatile("cp.async.wait_group 1;");
            __syncthreads();
            const int db = kc & 1;
            const __nv_bfloat16* Bh = (const __nv_bfloat16*)(smc + A_B + (db * 2 + 0) * A_B2SZ);
            const __nv_bfloat16* Bl = (const __nv_bfloat16*)(smc + A_B + (db * 2 + 1) * A_B2SZ);
#pragma unroll
            for (int kt = 0; kt < 2; kt++) {
                const int k0 = kc * 32 + kt * 16;
                frag_a ah[2], al[2];
#pragma unroll
                for (int m = 0; m < 2; m++) {
                    const int r0 = (wm * 2 + m) * 16;
                    wmma::load_matrix_sync(ah[m], Xh + r0 * XSTR + k0, XSTR);
                    wmma::load_matrix_sync(al[m], Xl + r0 * XSTR + k0, XSTR);
                }
                frag_b bh[2], bl[2];
#pragma unroll
                for (int n = 0; n < 2; n++) {
                    const int c0 = (wn * 2 + n) * 16;
                    wmma::load_matrix_sync(bh[n], Bh + kt * 16 * BSTR2 + c0, BSTR2);
                    wmma::load_matrix_sync(bl[n], Bl + kt * 16 * BSTR2 + c0, BSTR2);
                }
#pragma unroll
                for (int m = 0; m < 2; m++)
#pragma unroll
                    for (int n = 0; n < 2; n++) {
                        wmma::mma_sync(acc[m][n], ah[m], bh[n], acc[m][n]);
                        wmma::mma_sync(acc[m][n], ah[m], bl[n], acc[m][n]);
                        wmma::mma_sync(acc[m][n], al[m], bh[n], acc[m][n]);
                    }
            }
            __syncthreads();
        }
#pragma unroll
        for (int m = 0; m < 2; m++)
#pragma unroll
            for (int n = 0; n < 2; n++)
                wmma::store_matrix_sync(scratch + ((wm * 2 + m) * 16) * BSTR2 + (wn * 2 + n) * 16,
                                        acc[m][n], BSTR2, wmma::mem_row_major);
        __syncthreads();
        {
            int row = t >> 2, c0 = (t & 3) * 32;
            int node = nb + row;
            if (node < NN) {
                u32 hps[16], lps[16];
#pragma unroll
                for (int j = 0; j < 16; j++) {
                    int c = c0 + j * 2;
                    float v0 = fmaxf(scratch[row * BSTR2 + c]     + b1s[cn * 128 + c],     0.f);
                    float v1 = fmaxf(scratch[row * BSTR2 + c + 1] + b1s[cn * 128 + c + 1], 0.f);
                    u32 ph = pk2(v0, v1);
                    lps[j] = pk2(v0 - lof(ph), v1 - hif(ph));
                    hps[j] = ph;
                }
                u16* dh = g_Hh + (size_t)node * HID + cn * 128 + c0;
                u16* dl = g_Hl + (size_t)node * HID + cn * 128 + c0;
#pragma unroll
                for (int q = 0; q < 4; q++) {
                    *(uint4*)(dh + q * 8) = make_uint4(hps[q * 4], hps[q * 4 + 1],
                                                       hps[q * 4 + 2], hps[q * 4 + 3]);
                    *(uint4*)(dl + q * 8) = make_uint4(lps[q * 4], lps[q * 4 + 1],
                                                       lps[q * 4 + 2], lps[q * 4 + 3]);
                }
            }
        }
        __syncthreads();
    }
}

// =====================================================================
// mlpB: emb2 = H@W2 + b2. 64 nodes/CTA, 2 CTAs/SM, double-buffered.
// =====================================================================
#define BA_STR 72
#define B_A   0
#define B_ASZ (64 * BA_STR * 2)               // 9216
#define B_B   (4 * B_ASZ)                     // 36864
#define B_BSZ (64 * BSTR2 * 2)                // 17408
#define B_BIAS (B_B + 4 * B_BSZ)              // 106496
#define SMEM_B (B_BIAS + 128 * 4)             // 107008

__global__ __launch_bounds__(256, 2) void mlpB_kernel(const float* __restrict__ b2)
{
    extern __shared__ char smc[];
    float* b2s = (float*)(smc + B_BIAS);
    float* scratch = (float*)(smc + B_B);
    const int t = threadIdx.x;
    const int nb = blockIdx.x * NPC;
    const int w = t >> 5;
    const int wm = w & 1;
    const int wn = w >> 1;

    if (t < 128) b2s[t] = b2[t];

    auto stageA = [&](int kc, int db) {
        unsigned ah = sm_u32(smc + B_A + (db * 2 + 0) * B_ASZ);
        unsigned al = sm_u32(smc + B_A + (db * 2 + 1) * B_ASZ);
#pragma unroll
        for (int it = 0; it < 2; it++) {
            int task = t + it * 256;
            int row = task >> 3, col8 = (task & 7) * 8;
            int node = nb + row;
            unsigned d = (unsigned)(row * BA_STR + col8) * 2u;
            if (node < NN) {
                size_t s = (size_t)node * HID + kc * 64 + col8;
                cpa16(ah + d, g_Hh + s);
                cpa16(al + d, g_Hl + s);
            } else {
                *(uint4*)(smc + B_A + (db * 2 + 0) * B_ASZ + d) = make_uint4(0, 0, 0, 0);
                *(uint4*)(smc + B_A + (db * 2 + 1) * B_ASZ + d) = make_uint4(0, 0, 0, 0);
            }
        }
    };
    auto stageB = [&](int kc, int db) {
        unsigned bh = sm_u32(smc + B_B + (db * 2 + 0) * B_BSZ);
        unsigned bl = sm_u32(smc + B_B + (db * 2 + 1) * B_BSZ);
#pragma unroll
        for (int it = 0; it < 4; it++) {
            int task = t + it * 256;
            int row = task >> 4, col8 = (task & 15) * 8;
            unsigned d = (unsigned)(row * BSTR2 + col8) * 2u;
            size_t s = (size_t)(kc * 64 + row) * OUTD + col8;
            cpa16(bh + d, g_W2h + s);
            cpa16(bl + d, g_W2l + s);
        }
    };

    frag_c acc[2][2];
#pragma unroll
    for (int m = 0; m < 2; m++)
#pragma unroll
        for (int n = 0; n < 2; n++) wmma::fill_fragment(acc[m][n], 0.f);

    stageA(0, 0);
    stageB(0, 0);
    cpa_commit();
    for (int kc = 0; kc < 8; kc++) {
        if (kc < 7) { stageA(kc + 1, (kc + 1) & 1); stageB(kc + 1, (kc + 1) & 1); }
        cpa_commit();
        asm volatile("cp.async.wait_group 1;");
        __syncthreads();
        const int db = kc & 1;
        const __nv_bfloat16* Ah = (const __nv_bfloat16*)(smc + B_A + (db * 2 + 0) * B_ASZ);
        const __nv_bfloat16* Al = (const __nv_bfloat16*)(smc + B_A + (db * 2 + 1) * B_ASZ);
        const __nv_bfloat16* Bh = (const __nv_bfloat16*)(smc + B_B + (db * 2 + 0) * B_BSZ);
        const __nv_bfloat16* Bl = (const __nv_bfloat16*)(smc + B_B + (db * 2 + 1) * B_BSZ);
#pragma unroll
        for (int kt = 0; kt < 4; kt++) {
            const int k0 = kt * 16;
            frag_a ah[2], al[2];
#pragma unroll
            for (int m = 0; m < 2; m++) {
                const int r0 = (wm * 2 + m) * 16;
                wmma::load_matrix_sync(ah[m], Ah + r0 * BA_STR + k0, BA_STR);
                wmma::load_matrix_sync(al[m], Al + r0 * BA_STR + k0, BA_STR);
            }
            frag_b bh[2], bl[2];
#pragma unroll
            for (int n = 0; n < 2; n++) {
                const int c0 = (wn * 2 + n) * 16;
                wmma::load_matrix_sync(bh[n], Bh + kt * 16 * BSTR2 + c0, BSTR2);
                wmma::load_matrix_sync(bl[n], Bl + kt * 16 * BSTR2 + c0, BSTR2);
            }
#pragma unroll
            for (int m = 0; m < 2; m++)
#pragma unroll
                for (int n = 0; n < 2; n++) {
                    wmma::mma_sync(acc[m][n], ah[m], bh[n], acc[m][n]);
                    wmma::mma_sync(acc[m][n], ah[m], bl[n], acc[m][n]);
                    wmma::mma_sync(acc[m][n], al[m], bh[n], acc[m][n]);
                }
        }
        __syncthreads();
    }

#pragma unroll
    for (int m = 0; m < 2; m++)
#pragma unroll
        for (int n = 0; n < 2; n++)
            wmma::store_matrix_sync(scratch + ((wm * 2 + m) * 16) * BSTR2 + (wn * 2 + n) * 16,
                                    acc[m][n], BSTR2, wmma::mem_row_major);
    __syncthreads();
    {
        int row = t >> 2, c0 = (t & 3) * 32;
        int node = nb + row;
        if (node < NN) {
#pragma unroll
            for (int q = 0; q < 8; q++) {
                float4 o;
                o.x = scratch[row * BSTR2 + c0 + q * 4 + 0] + b2s[c0 + q * 4 + 0];
                o.y = scratch[row * BSTR2 + c0 + q * 4 + 1] + b2s[c0 + q * 4 + 1];
                o.z = scratch[row * BSTR2 + c0 + q * 4 + 2] + b2s[c0 + q * 4 + 2];
                o.w = scratch[row * BSTR2 + c0 + q * 4 + 3] + b2s[c0 + q * 4 + 3];
                *(float4*)(g_emb2 + (size_t)node * OUTD + c0 + q * 4) = o;
            }
        }
    }
}

// =====================================================================
// edge kernel (unchanged)
// =====================================================================
__global__ __launch_bounds__(256) void edge_kernel(
    const int* __restrict__ en, float C, int perm_edges)
{
    const int lane = threadIdx.x & 31;
    const int e    = blockIdx.x * 8 + (threadIdx.x >> 5);

    int myn = 0;
    if (lane < 4) myn = en[e * 4 + lane];
    const unsigned m = 0xffffffffu;
    int n0 = __shfl_sync(m, myn, 0);
    int n1 = __shfl_sync(m, myn, 1);
    int n2 = __shfl_sync(m, myn, 2);
    int n3 = __shfl_sync(m, myn, 3);

    float2 g0 = *(const float2*)(g_scaled + (size_t)n0 * RANK + lane * 2);
    float2 g1 = *(const float2*)(g_scaled + (size_t)n1 * RANK + lane * 2);
    float2 g2 = *(const float2*)(g_scaled + (size_t)n2 * RANK + lane * 2);
    float2 g3 = *(const float2*)(g_scaled + (size_t)n3 * RANK + lane * 2);

    float2 a, b;
    a.x = g0.x * g1.x; a.y = g0.y * g1.y;
    b.x = g2.x * g3.x; b.y = g2.y * g3.y;
    float2 t0, t1, t2, t3;
    t0.x = tanhf(C * (g1.x * b.x)); t0.y = tanhf(C * (g1.y * b.y));
    t1.x = tanhf(C * (g0.x * b.x)); t1.y = tanhf(C * (g0.y * b.y));
    t2.x = tanhf(C * (a.x * g3.x)); t2.y = tanhf(C * (a.y * g3.y));
    t3.x = tanhf(C * (a.x * g2.x)); t3.y = tanhf(C * (a.y * g2.y));

    const int d = e / perm_edges;
    *(float2*)(g_term + ((size_t)n0 * DD + d) * RANK + lane * 2) = t0;
    *(float2*)(g_term + ((size_t)n1 * DD + d) * RANK + lane * 2) = t1;
    *(float2*)(g_term + ((size_t)n2 * DD + d) * RANK + lane * 2) = t2;
    *(float2*)(g_term + ((size_t)n3 * DD + d) * RANK + lane * 2) = t3;
    if (lane < 4) g_eidx[(size_t)myn * DD + d] = e;

    float4 s = make_float4(0.f, 0.f, 0.f, 0.f);
    float4 v;
    v = *(const float4*)(g_emb2 + (size_t)n0 * OUTD + lane * 4);
    s.x += v.x; s.y += v.y; s.z += v.z; s.w += v.w;
    v = *(const float4*)(g_emb2 + (size_t)n1 * OUTD + lane * 4);
    s.x += v.x; s.y += v.y; s.z += v.z; s.w += v.w;
    v = *(const float4*)(g_emb2 + (size_t)n2 * OUTD + lane * 4);
    s.x += v.x; s.y += v.y; s.z += v.z; s.w += v.w;
    v = *(const float4*)(g_emb2 + (size_t)n3 * OUTD + lane * 4);
    s.x += v.x; s.y += v.y; s.z += v.z; s.w += v.w;
    s.x = fmaxf(s.x, 0.f); s.y = fmaxf(s.y, 0.f);
    s.z = fmaxf(s.z, 0.f); s.w = fmaxf(s.w, 0.f);
    *(float4*)(g_redge2 + (size_t)e * OUTD + lane * 4) = s;
}

// =====================================================================
// out kernel (unchanged)
// =====================================================================
__global__ __launch_bounds__(256) void out_kernel(
    const float* __restrict__ Wq, const float* __restrict__ bq,
    float* __restrict__ out, float degf, float invdeg)
{
    __shared__ float tsums[32 * RANK];
    __shared__ float Wqs[RANK * OUTD];
    __shared__ int   eixs[32 * DD];
    const int t  = threadIdx.x;
    const int nb = blockIdx.x * 32;

    {
        const float4* ws = (const float4*)Wq;
        float4* wd = (float4*)Wqs;
#pragma unroll
        for (int i = 0; i < 8; i++) wd[t + i * 256] = ws[t + i * 256];
    }
    eixs[t] = g_eidx[(size_t)nb * DD + t];

    {
        const int n = t >> 3;
        const int p = (t & 7) * 8;
        const float* src = g_term + (size_t)(nb + n) * DD * RANK + p;
        float4 s0 = make_float4(0.f, 0.f, 0.f, 0.f);
        float4 s1 = make_float4(0.f, 0.f, 0.f, 0.f);
#pragma unroll
        for (int d = 0; d < DD; d++) {
            float4 v0 = *(const float4*)(src + d * RANK);
            float4 v1 = *(const float4*)(src + d * RANK + 4);
            s0.x += v0.x; s0.y += v0.y; s0.z += v0.z; s0.w += v0.w;
            s1.x += v1.x; s1.y += v1.y; s1.z += v1.z; s1.w += v1.w;
        }
        *(float4*)(tsums + n * RANK + p)     = s0;
        *(float4*)(tsums + n * RANK + p + 4) = s1;
    }
    __syncthreads();

    const int n0 = (t >> 4) * 2;
    const int cg = t & 15;
    u64 acc[2][4];
#pragma unroll
    for (int r = 0; r < 2; r++)
#pragma unroll
        for (int j = 0; j < 4; j++) acc[r][j] = 0;

#pragma unroll
    for (int k4 = 0; k4 < RANK / 4; k4++) {
        float4 a40 = *(const float4*)(tsums + n0 * RANK + k4 * 4);
        float4 a41 = *(const float4*)(tsums + (n0 + 1) * RANK + k4 * 4);
#pragma unroll
        for (int kk = 0; kk < 4; kk++) {
            int k = k4 * 4 + kk;
            ulonglong2 b0 = *(const ulonglong2*)(Wqs + k * OUTD + 4 * cg);
            ulonglong2 b1v = *(const ulonglong2*)(Wqs + k * OUTD + 64 + 4 * cg);
            u64 av0 = bcast2(((const float*)&a40)[kk]);
            u64 av1 = bcast2(((const float*)&a41)[kk]);
            acc[0][0] = f2fma(av0, b0.x,  acc[0][0]);
            acc[0][1] = f2fma(av0, b0.y,  acc[0][1]);
            acc[0][2] = f2fma(av0, b1v.x, acc[0][2]);
            acc[0][3] = f2fma(av0, b1v.y, acc[0][3]);
            acc[1][0] = f2fma(av1, b0.x,  acc[1][0]);
            acc[1][1] = f2fma(av1, b0.y,  acc[1][1]);
            acc[1][2] = f2fma(av1, b1v.x, acc[1][2]);
            acc[1][3] = f2fma(av1, b1v.y, acc[1][3]);
        }
    }

    float4 bv0 = *(const float4*)(bq + 4 * cg);
    float4 bv1 = *(const float4*)(bq + 64 + 4 * cg);
    const float* bb0 = (const float*)&bv0;
    const float* bb1 = (const float*)&bv1;

#pragma unroll
    for (int r = 0; r < 2; r++) {
        const int n = n0 + r;
        float4 r0 = make_float4(0.f, 0.f, 0.f, 0.f);
        float4 r1 = make_float4(0.f, 0.f, 0.f, 0.f);
#pragma unroll
        for (int d = 0; d < DD; d++) {
            int e = eixs[n * DD + d];
            float4 v0 = *(const float4*)(g_redge2 + (size_t)e * OUTD + 4 * cg);
            float4 v1 = *(const float4*)(g_redge2 + (size_t)e * OUTD + 64 + 4 * cg);
            r0.x += v0.x; r0.y += v0.y; r0.z += v0.z; r0.w += v0.w;
            r1.x += v1.x; r1.y += v1.y; r1.z += v1.z; r1.w += v1.w;
        }
        float o[8];
        upk2(acc[r][0], o[0], o[1]); upk2(acc[r][1], o[2], o[3]);
        upk2(acc[r][2], o[4], o[5]); upk2(acc[r][3], o[6], o[7]);
        const float* rr0 = (const float*)&r0;
        const float* rr1 = (const float*)&r1;
        float4 w0, w1v;
        w0.x = fmaxf((o[0] + degf * bb0[0] + rr0[0]) * invdeg, 0.f);
        w0.y = fmaxf((o[1] + degf * bb0[1] + rr0[1]) * invdeg, 0.f);
        w0.z = fmaxf((o[2] + degf * bb0[2] + rr0[2]) * invdeg, 0.f);
        w0.w = fmaxf((o[3] + degf * bb0[3] + rr0[3]) * invdeg, 0.f);
        w1v.x = fmaxf((o[4] + degf * bb1[0] + rr1[0]) * invdeg, 0.f);
        w1v.y = fmaxf((o[5] + degf * bb1[1] + rr1[1]) * invdeg, 0.f);
        w1v.z = fmaxf((o[6] + degf * bb1[2] + rr1[2]) * invdeg, 0.f);
        w1v.w = fmaxf((o[7] + degf * bb1[3] + rr1[3]) * invdeg, 0.f);
        *(float4*)(out + (size_t)(nb + n) * OUTD + 4 * cg)      = w0;
        *(float4*)(out + (size_t)(nb + n) * OUTD + 64 + 4 * cg) = w1v;
    }
}

// =====================================================================
extern "C" void kernel_launch(void* const* d_in, const int* in_sizes, int n_in,
                              void* d_out, int out_size)
{
    const float* X  = (const float*)d_in[0];
    const float* Wp = (const float*)d_in[1];
    const float* bp = (const float*)d_in[2];
    const float* Wq = (const float*)d_in[3];
    const float* bq = (const float*)d_in[4];
    const float* W1 = (const float*)d_in[5];
    const float* b1 = (const float*)d_in[6];
    const float* W2 = (const float*)d_in[7];
    const float* b2 = (const float*)d_in[8];
    const int*   en = (const int*)d_in[9];

    const int N  = in_sizes[0] / FEAT;
    const int EK = in_sizes[9];
    const int E  = EK / KK;
    const int deg = EK / N;
    const float num = powf((float)deg, 1.0f / (float)KK);
    const float C   = num * (1.0f / 6.0f);
    const int perm_edges = N / KK;

    cudaFuncSetAttribute(mlpA_kernel, cudaFuncAttributeMaxDynamicSharedMemorySize, SMEM_A);
    cudaFuncSetAttribute(mlpB_kernel, cudaFuncAttributeMaxDynamicSharedMemorySize, SMEM_B);

    prep_w_kernel<<<(FEAT * HID) / 256, 256>>>(Wp, W1, W2);
    mlpA_kernel<<<CTAS_MLP, 256, SMEM_A>>>(X, bp, b1, num);
    mlpB_kernel<<<CTAS_MLP, 256, SMEM_B>>>(b2);
    edge_kernel<<<E / 8, 256>>>(en, C, perm_edges);
    out_kernel<<<N / 32, 256>>>(Wq, bq, (float*)d_out, (float)deg, 1.0f / (float)deg);
}